// round 7
// baseline (speedup 1.0000x reference)
#include <cuda_runtime.h>
#include <cuda_bf16.h>
#include <mma.h>
#include <math.h>

using namespace nvcuda;

#define D      512
#define KWTA   128
#define MAXB   8192

// GEMM tiling
#define BM     128
#define BN     128
#define BK     64
#define NK     (D / BK)          // 8
#define LDAS   72                // A smem leading dim (bf16)
#define LDBS   136               // B smem leading dim (bf16)
#define LDE    132               // f32 epilogue staging leading dim
#define STAGE_E (BM * LDAS + BK * LDBS)          // 17920 bf16 per stage
#define SMEM_GEMM (3 * STAGE_E * 2)              // 107520 bytes

// ---------------- device scratch ----------------
__device__ __nv_bfloat16 g_Wb[D * D];            // W   [O][I]  (pred)
__device__ __nv_bfloat16 g_WTb[D * D];           // W^T [I][O]  (feedback)
__device__ __nv_bfloat16 g_V15b[D * D];          // 1.5 V [I][O]
__device__ __nv_bfloat16 g_Rb[D * D];
__device__ __nv_bfloat16 g_Rgb[D * D];
__device__ __nv_bfloat16 g_Lb[D * D];

__device__ __nv_bfloat16 g_phix[MAXB * D];
__device__ __nv_bfloat16 g_bub[MAXB * D];
__device__ __nv_bfloat16 g_ctx[MAXB * D];
__device__ __nv_bfloat16 g_phic[MAXB * D];
__device__ __nv_bfloat16 g_phid[MAXB * D];
__device__ __nv_bfloat16 g_tdx[MAXB * D];        // 3 td - 5.5 x - 1e-6 sign(x)
__device__ __nv_bfloat16 g_err[MAXB * D];
__device__ __nv_bfloat16 g_P1a[MAXB * D];        // phix@L + 1.5 b_in + tdx
__device__ __nv_bfloat16 g_fwd15[MAXB * D];      // bub@(1.5V)
__device__ __nv_bfloat16 g_gate[MAXB * D];
__device__ __nv_bfloat16 g_rec[MAXB * D];
__device__ __nv_bfloat16 g_g[MAXB * D];

__device__ float g_part[(MAXB / BM) * (D / BN)];
__device__ float g_scalef;

// ---------------- weight conversion ----------------
__global__ void convert_kernel(const float* __restrict__ W, const float* __restrict__ V,
                               const float* __restrict__ R, const float* __restrict__ Rg,
                               const float* __restrict__ L) {
    int n = D * D;
    for (int idx = blockIdx.x * blockDim.x + threadIdx.x; idx < n; idx += gridDim.x * blockDim.x) {
        int i = idx >> 9, j = idx & 511;
        float w = W[idx];
        g_Wb[idx]        = __float2bfloat16(w);
        g_WTb[j * D + i] = __float2bfloat16(w);
        g_V15b[idx]      = __float2bfloat16(1.5f * V[idx]);
        g_Rb[idx]        = __float2bfloat16(R[idx]);
        g_Rgb[idx]       = __float2bfloat16(Rg[idx]);
        g_Lb[idx]        = __float2bfloat16(L[idx]);
    }
}

// ---------------- exact register k-WTA (top-128 of 512, stable ties) -------
__device__ __forceinline__ void kwta_reg(const float v[16], float m[16]) {
    int lane = threadIdx.x & 31;
    unsigned u[16];
#pragma unroll
    for (int j = 0; j < 16; j++) {
        unsigned b = __float_as_uint(v[j]);
        u[j] = (b & 0x80000000u) ? ~b : (b | 0x80000000u);
    }
    unsigned prefix = 0;
    for (int bit = 31; bit >= 0; --bit) {
        unsigned probe = prefix | (1u << bit);
        int c = 0;
#pragma unroll
        for (int j = 0; j < 16; j++) c += (u[j] >= probe);
        c = __reduce_add_sync(0xffffffffu, c);
        if (c >= KWTA) prefix = probe;
    }
    int cg = 0;
#pragma unroll
    for (int j = 0; j < 16; j++) cg += (u[j] > prefix);
    cg = __reduce_add_sync(0xffffffffu, cg);
    int remk = KWTA - cg;
    unsigned lmask = (1u << lane) - 1u;
    int running = 0;
#pragma unroll
    for (int j = 0; j < 16; j++) {
        bool eq = (u[j] == prefix);
        unsigned beq = __ballot_sync(0xffffffffu, eq);
        bool inc = (u[j] > prefix) || (eq && (running + __popc(beq & lmask)) < remk);
        running += __popc(beq);
        m[j] = inc ? 1.0f : 0.0f;
    }
}

// ---------------- elementwise precompute (one warp per batch row) ----------
__global__ void __launch_bounds__(256) elemwise_kernel(
    const float* __restrict__ x, const float* __restrict__ xt1,
    const float* __restrict__ xt2, const float* __restrict__ xt3,
    const float* __restrict__ bu, const float* __restrict__ td) {
    const int warp = threadIdx.x >> 5, lane = threadIdx.x & 31;
    const size_t base = ((size_t)blockIdx.x * 8 + warp) * D;
    const float INV_SQRT2 = 0.70710678118654752440f;
    const float INV_SQRT2PI = 0.39894228040143267794f;

    float v[16], m[16];
#pragma unroll
    for (int j = 0; j < 16; j++) v[j] = x[base + lane + 32 * j];
    kwta_reg(v, m);
#pragma unroll
    for (int j = 0; j < 16; j++) {
        size_t idx = base + lane + 32 * j;
        float val = v[j];
        float cdf = 0.5f * (1.0f + erff(val * INV_SQRT2));
        float pdf = __expf(-0.5f * val * val) * INV_SQRT2PI;
        g_phix[idx] = __float2bfloat16(val * cdf * m[j]);
        g_phid[idx] = __float2bfloat16((cdf + val * pdf) * m[j]);
        g_bub[idx]  = __float2bfloat16(bu[idx]);
        float sgn = (val > 0.0f) ? 1.0f : ((val < 0.0f) ? -1.0f : 0.0f);
        g_tdx[idx]  = __float2bfloat16(3.0f * td[idx] - 5.5f * val - 1e-6f * sgn);
    }
    float c[16];
#pragma unroll
    for (int j = 0; j < 16; j++) {
        size_t idx = base + lane + 32 * j;
        c[j] = 0.5f * xt1[idx] + 0.3f * xt2[idx] + 0.2f * xt3[idx];
    }
    kwta_reg(c, m);
#pragma unroll
    for (int j = 0; j < 16; j++) {
        size_t idx = base + lane + 32 * j;
        float val = c[j];
        g_ctx[idx] = __float2bfloat16(val);
        float cdf = 0.5f * (1.0f + erff(val * INV_SQRT2));
        g_phic[idx] = __float2bfloat16(val * cdf * m[j]);
    }
}

// ---------------- cp.async helpers ----------------
__device__ __forceinline__ void cp16(void* s, const void* g) {
    unsigned sa = (unsigned)__cvta_generic_to_shared(s);
    asm volatile("cp.async.cg.shared.global [%0], [%1], 16;" :: "r"(sa), "l"(g));
}

// A tile: 128x64 bf16 (1024 chunks), B tile: 64x128 bf16 (1024 chunks)
__device__ __forceinline__ void load_stage(__nv_bfloat16* stage,
                                           const __nv_bfloat16* Ag,
                                           const __nv_bfloat16* Bg,
                                           int k0, int tid) {
    __nv_bfloat16* As = stage;
    __nv_bfloat16* Bs = stage + BM * LDAS;
#pragma unroll
    for (int t = 0; t < 4; t++) {
        int id = tid + t * 256;
        int ar = id >> 3, ac = id & 7;
        cp16(As + ar * LDAS + ac * 8, Ag + (size_t)ar * D + k0 + ac * 8);
        int br = id >> 4, bc = id & 15;
        cp16(Bs + br * LDBS + bc * 8, Bg + (size_t)(k0 + br) * D + bc * 8);
    }
}

// ---------------- pipelined GEMM (+ mode-specific fused epilogue) ----------
// mode 0: err   = bub - (phix@W + b_out)                 -> bf16
// mode 1: P1a   = phix@L + 1.5 b_in + tdx                -> bf16
// mode 2: fwd15 = bub@(1.5V)                             -> bf16
// mode 3: gate  = sigmoid(ctx@Rg)                        -> bf16
// mode 4: rec   = phic@R                                 -> bf16
// mode 5: fb    = err@W^T; g = fb*phid + P1a + fwd15 + rec*gate -> bf16 + sumsq
__global__ void __launch_bounds__(256) gemm_kernel(
    int mode_base, const float* __restrict__ b_in, const float* __restrict__ b_out) {
    extern __shared__ unsigned char smem_raw[];
    __nv_bfloat16* smem = (__nv_bfloat16*)smem_raw;
    __shared__ float red[256];

    const int tid = threadIdx.x, wid = tid >> 5;
    const int wm = wid >> 2, wn = wid & 3;
    const int mode = (mode_base < 0) ? (int)blockIdx.z : mode_base;
    const int n0 = blockIdx.x * BN, m0 = blockIdx.y * BM;

    const __nv_bfloat16 *A, *B;
    switch (mode) {
        case 0: A = g_phix; B = g_Wb;   break;
        case 1: A = g_phix; B = g_Lb;   break;
        case 2: A = g_bub;  B = g_V15b; break;
        case 3: A = g_ctx;  B = g_Rgb;  break;
        case 4: A = g_phic; B = g_Rb;   break;
        default: A = g_err; B = g_WTb;  break;
    }
    const __nv_bfloat16* Ag = A + (size_t)m0 * D;
    const __nv_bfloat16* Bg = B + n0;

    wmma::fragment<wmma::accumulator, 16, 16, 16, float> acc[4][2];
#pragma unroll
    for (int i = 0; i < 4; i++)
#pragma unroll
        for (int j = 0; j < 2; j++) wmma::fill_fragment(acc[i][j], 0.0f);

    load_stage(smem + 0 * STAGE_E, Ag, Bg, 0, tid);
    asm volatile("cp.async.commit_group;" ::: "memory");
    load_stage(smem + 1 * STAGE_E, Ag, Bg, BK, tid);
    asm volatile("cp.async.commit_group;" ::: "memory");

    for (int ki = 0; ki < NK; ki++) {
        asm volatile("cp.async.wait_group 1;" ::: "memory");
        __syncthreads();
        __nv_bfloat16* As = smem + (ki % 3) * STAGE_E;
        __nv_bfloat16* Bs = As + BM * LDAS;
#pragma unroll
        for (int kk = 0; kk < BK; kk += 16) {
            wmma::fragment<wmma::matrix_a, 16, 16, 16, __nv_bfloat16, wmma::row_major> af[4];
            wmma::fragment<wmma::matrix_b, 16, 16, 16, __nv_bfloat16, wmma::row_major> bf_[2];
#pragma unroll
            for (int i = 0; i < 4; i++)
                wmma::load_matrix_sync(af[i], As + (wm * 64 + i * 16) * LDAS + kk, LDAS);
#pragma unroll
            for (int j = 0; j < 2; j++)
                wmma::load_matrix_sync(bf_[j], Bs + kk * LDBS + wn * 32 + j * 16, LDBS);
#pragma unroll
            for (int i = 0; i < 4; i++)
#pragma unroll
                for (int j = 0; j < 2; j++)
                    wmma::mma_sync(acc[i][j], af[i], bf_[j], acc[i][j]);
        }
        if (ki + 2 < NK) load_stage(smem + ((ki + 2) % 3) * STAGE_E, Ag, Bg, (ki + 2) * BK, tid);
        asm volatile("cp.async.commit_group;" ::: "memory");
    }
    asm volatile("cp.async.wait_group 0;" ::: "memory");

    // epilogue: 64 rows at a time staged through (reused) pipeline smem
    float* Es = (float*)smem_raw;
    float ss = 0.0f;
#pragma unroll 1
    for (int half = 0; half < 2; half++) {
        __syncthreads();
        if (wm == half)
#pragma unroll
            for (int i = 0; i < 4; i++)
#pragma unroll
                for (int j = 0; j < 2; j++)
                    wmma::store_matrix_sync(Es + (i * 16) * LDE + wn * 32 + j * 16,
                                            acc[i][j], LDE, wmma::mem_row_major);
        __syncthreads();
#pragma unroll 4
        for (int t = 0; t < 32; t++) {
            int idx = t * 256 + tid;
            int r = idx >> 7, c = idx & 127;
            int gc = n0 + c;
            size_t gi = (size_t)(m0 + half * 64 + r) * D + gc;
            float v = Es[r * LDE + c];
            switch (mode) {
                case 0: {
                    float pred = v + b_out[gc];
                    g_err[gi] = __float2bfloat16(__bfloat162float(g_bub[gi]) - pred);
                } break;
                case 1:
                    g_P1a[gi] = __float2bfloat16(v + 1.5f * b_in[gc] + __bfloat162float(g_tdx[gi]));
                    break;
                case 2: g_fwd15[gi] = __float2bfloat16(v); break;
                case 3: g_gate[gi] = __float2bfloat16(1.0f / (1.0f + __expf(-v))); break;
                case 4: g_rec[gi] = __float2bfloat16(v); break;
                default: {
                    float g = v * __bfloat162float(g_phid[gi]) + __bfloat162float(g_P1a[gi])
                              + __bfloat162float(g_fwd15[gi])
                              + __bfloat162float(g_rec[gi]) * __bfloat162float(g_gate[gi]);
                    g_g[gi] = __float2bfloat16(g);
                    ss += g * g;
                } break;
            }
        }
    }

    if (mode == 5) {
        red[tid] = ss;
        __syncthreads();
        for (int o = 128; o > 0; o >>= 1) {
            if (tid < o) red[tid] += red[tid + o];
            __syncthreads();
        }
        if (tid == 0) g_part[blockIdx.y * gridDim.x + blockIdx.x] = red[0];
    }
}

// ---------------- global norm -> clip scale ----------------
__global__ void reduce_scale_kernel(const int* __restrict__ step_i, int nparts) {
    __shared__ float red[256];
    float s = 0.0f;
    for (int i = threadIdx.x; i < nparts; i += 256) s += g_part[i];
    red[threadIdx.x] = s;
    __syncthreads();
    for (int o = 128; o > 0; o >>= 1) {
        if (threadIdx.x < o) red[threadIdx.x] += red[threadIdx.x + o];
        __syncthreads();
    }
    if (threadIdx.x == 0) {
        float eta = 0.8f / (1.0f + 0.1f * (float)step_i[0]);
        float cc = 0.5f * eta;                   // TAU * eta
        float n = cc * sqrtf(red[0]);
        float sc = (n > 1.0f) ? (1.0f / (n + 1e-8f)) : 1.0f;
        g_scalef = cc * sc;
    }
}

// ---------------- finalize: x_new = clip(x + g*scale, -5, 5) ----------------
__global__ void finalize_kernel(const float* __restrict__ x, float* __restrict__ out, int n2) {
    float f = g_scalef;
    const float2* x2 = (const float2*)x;
    const __nv_bfloat162* gg = (const __nv_bfloat162*)g_g;
    float2* o2 = (float2*)out;
    for (int i = blockIdx.x * blockDim.x + threadIdx.x; i < n2; i += gridDim.x * blockDim.x) {
        float2 xv = x2[i];
        float2 gv = __bfloat1622float2(gg[i]);
        float2 o;
        o.x = fminf(5.0f, fmaxf(-5.0f, xv.x + gv.x * f));
        o.y = fminf(5.0f, fmaxf(-5.0f, xv.y + gv.y * f));
        o2[i] = o;
    }
}

extern "C" void kernel_launch(void* const* d_in, const int* in_sizes, int n_in,
                              void* d_out, int out_size) {
    const float* bu    = (const float*)d_in[0];
    const float* td    = (const float*)d_in[1];
    const float* x     = (const float*)d_in[2];
    const float* xt1   = (const float*)d_in[3];
    const float* xt2   = (const float*)d_in[4];
    const float* xt3   = (const float*)d_in[5];
    const float* V     = (const float*)d_in[6];
    const float* b_in  = (const float*)d_in[7];
    const float* W     = (const float*)d_in[8];
    const float* b_out = (const float*)d_in[9];
    const float* R     = (const float*)d_in[10];
    const float* Rg    = (const float*)d_in[11];
    const float* L     = (const float*)d_in[12];
    const int*   step  = (const int*)d_in[13];

    int Btot = in_sizes[2] / D;
    if (Btot > MAXB) Btot = MAXB;
    int mtiles = Btot / BM;             // 64

    cudaFuncSetAttribute(gemm_kernel, cudaFuncAttributeMaxDynamicSharedMemorySize, SMEM_GEMM);

    convert_kernel<<<128, 256>>>(W, V, R, Rg, L);
    elemwise_kernel<<<Btot / 8, 256>>>(x, xt1, xt2, xt3, bu, td);
    gemm_kernel<<<dim3(D / BN, mtiles, 5), 256, SMEM_GEMM>>>(-1, b_in, b_out);
    gemm_kernel<<<dim3(D / BN, mtiles, 1), 256, SMEM_GEMM>>>(5, b_in, b_out);
    reduce_scale_kernel<<<1, 256>>>(step, mtiles * (D / BN));
    finalize_kernel<<<1024, 256>>>(x, (float*)d_out, Btot * D / 2);
}

// round 8
// speedup vs baseline: 1.5355x; 1.5355x over previous
#include <cuda_runtime.h>
#include <cuda_bf16.h>
#include <mma.h>
#include <math.h>

using namespace nvcuda;

#define D      512
#define KWTA   128
#define MAXB   8192

// GEMM tiling (R3-proven config: 56.8KB smem -> 2 CTAs/SM)
#define BM     128
#define BN     128
#define BK     32
#define LDAS   40
#define LDBS   136
#define LDE    132
#define STAGE_E (BM * LDAS + BK * LDBS)          // 9472 bf16 per stage
#define SMEM_GEMM (3 * STAGE_E * 2)              // 56832 bytes

#define NPART  1024

// ---------------- device scratch ----------------
__device__ __nv_bfloat16 g_Wb[D * D];            // W [O][I] row-major
__device__ __nv_bfloat16 g_WTb[D * D];           // W^T: [I][O], [i][o] = W[o][i]
__device__ __nv_bfloat16 g_nWWT[D * D];          // -(W W^T)  [m][o]
__device__ __nv_bfloat16 g_V15b[D * D];          // 1.5 V
__device__ __nv_bfloat16 g_Rb[D * D];
__device__ __nv_bfloat16 g_Rgb[D * D];
__device__ __nv_bfloat16 g_Lb[D * D];
__device__ float g_cvec[D];                      // c[o] = sum_i b_out[i] W[o][i]

__device__ __nv_bfloat16 g_phix[MAXB * D];
__device__ __nv_bfloat16 g_bub[MAXB * D];
__device__ __nv_bfloat16 g_ctx[MAXB * D];
__device__ __nv_bfloat16 g_phic[MAXB * D];
__device__ __nv_bfloat16 g_phid[MAXB * D];
__device__ __nv_bfloat16 g_tdx[MAXB * D];        // 3 td - 5.5 x - 1e-6 sign(x)
__device__ __nv_bfloat16 g_fb[MAXB * D];         // bu@W^T - phix@WWT - c
__device__ __nv_bfloat16 g_P1[MAXB * D];         // phix@L + bu@(1.5V) + 1.5 b_in + tdx
__device__ __nv_bfloat16 g_gate[MAXB * D];
__device__ __nv_bfloat16 g_rec[MAXB * D];
__device__ __nv_bfloat16 g_g[MAXB * D];

__device__ float g_part[NPART];
__device__ float g_scalef;

// ---------------- weight conversion ----------------
__global__ void convert_kernel(const float* __restrict__ W, const float* __restrict__ V,
                               const float* __restrict__ R, const float* __restrict__ Rg,
                               const float* __restrict__ L) {
    int n = D * D;
    for (int idx = blockIdx.x * blockDim.x + threadIdx.x; idx < n; idx += gridDim.x * blockDim.x) {
        int i = idx >> 9, j = idx & 511;
        float w = W[idx];
        g_Wb[idx]        = __float2bfloat16(w);
        g_WTb[j * D + i] = __float2bfloat16(w);
        g_V15b[idx]      = __float2bfloat16(1.5f * V[idx]);
        g_Rb[idx]        = __float2bfloat16(R[idx]);
        g_Rgb[idx]       = __float2bfloat16(Rg[idx]);
        g_Lb[idx]        = __float2bfloat16(L[idx]);
    }
}

// ---------------- WWT = W @ W^T (negated, bf16), 512x512x512 ----------------
// grid (4,4), 256 threads. M[m][o] = sum_i W[m][i] W[o][i].
__global__ void __launch_bounds__(256) wwt_kernel() {
    __shared__ float Es[64 * LDE];
    const int tid = threadIdx.x, wid = tid >> 5;
    const int wm = wid >> 2, wn = wid & 3;
    const int m0 = blockIdx.y * BM, n0 = blockIdx.x * BN;

    wmma::fragment<wmma::accumulator, 16, 16, 16, float> acc[4][2];
#pragma unroll
    for (int i = 0; i < 4; i++)
#pragma unroll
        for (int j = 0; j < 2; j++) wmma::fill_fragment(acc[i][j], 0.0f);

    for (int k = 0; k < D; k += 16) {
        wmma::fragment<wmma::matrix_a, 16, 16, 16, __nv_bfloat16, wmma::row_major> af[4];
        wmma::fragment<wmma::matrix_b, 16, 16, 16, __nv_bfloat16, wmma::row_major> bf_[2];
#pragma unroll
        for (int i = 0; i < 4; i++)
            wmma::load_matrix_sync(af[i], g_Wb + (size_t)(m0 + wm * 64 + i * 16) * D + k, D);
#pragma unroll
        for (int j = 0; j < 2; j++)
            wmma::load_matrix_sync(bf_[j], g_WTb + (size_t)k * D + n0 + wn * 32 + j * 16, D);
#pragma unroll
        for (int i = 0; i < 4; i++)
#pragma unroll
            for (int j = 0; j < 2; j++)
                wmma::mma_sync(acc[i][j], af[i], bf_[j], acc[i][j]);
    }
#pragma unroll 1
    for (int half = 0; half < 2; half++) {
        __syncthreads();
        if (wm == half)
#pragma unroll
            for (int i = 0; i < 4; i++)
#pragma unroll
                for (int j = 0; j < 2; j++)
                    wmma::store_matrix_sync(Es + (i * 16) * LDE + wn * 32 + j * 16,
                                            acc[i][j], LDE, wmma::mem_row_major);
        __syncthreads();
#pragma unroll 4
        for (int t = 0; t < 32; t++) {
            int idx = t * 256 + tid;
            int r = idx >> 7, c = idx & 127;
            g_nWWT[(size_t)(m0 + half * 64 + r) * D + n0 + c] = __float2bfloat16(-Es[r * LDE + c]);
        }
    }
}

// ---------------- c[o] = sum_i b_out[i] * W[o][i] ----------------
__global__ void cvec_kernel(const float* __restrict__ W, const float* __restrict__ b_out) {
    int gw = (blockIdx.x * blockDim.x + threadIdx.x) >> 5;   // global warp id
    int lane = threadIdx.x & 31;
    int nw = (gridDim.x * blockDim.x) >> 5;
    for (int row = gw; row < D; row += nw) {
        float s = 0.0f;
        for (int j = 0; j < 16; j++) {
            int i = lane + 32 * j;
            s += b_out[i] * W[(size_t)row * D + i];
        }
#pragma unroll
        for (int o = 16; o > 0; o >>= 1) s += __shfl_xor_sync(0xffffffffu, s, o);
        if (lane == 0) g_cvec[row] = s;
    }
}

// ---------------- exact register k-WTA (top-128 of 512, stable ties) -------
__device__ __forceinline__ void kwta_reg(const float v[16], float m[16]) {
    int lane = threadIdx.x & 31;
    unsigned u[16];
#pragma unroll
    for (int j = 0; j < 16; j++) {
        unsigned b = __float_as_uint(v[j]);
        u[j] = (b & 0x80000000u) ? ~b : (b | 0x80000000u);
    }
    unsigned prefix = 0;
    for (int bit = 31; bit >= 0; --bit) {
        unsigned probe = prefix | (1u << bit);
        int c = 0;
#pragma unroll
        for (int j = 0; j < 16; j++) c += (u[j] >= probe);
        c = __reduce_add_sync(0xffffffffu, c);
        if (c >= KWTA) prefix = probe;
    }
    int cg = 0;
#pragma unroll
    for (int j = 0; j < 16; j++) cg += (u[j] > prefix);
    cg = __reduce_add_sync(0xffffffffu, cg);
    int remk = KWTA - cg;
    unsigned lmask = (1u << lane) - 1u;
    int running = 0;
#pragma unroll
    for (int j = 0; j < 16; j++) {
        bool eq = (u[j] == prefix);
        unsigned beq = __ballot_sync(0xffffffffu, eq);
        bool inc = (u[j] > prefix) || (eq && (running + __popc(beq & lmask)) < remk);
        running += __popc(beq);
        m[j] = inc ? 1.0f : 0.0f;
    }
}

// ---------------- elementwise precompute (one warp per batch row) ----------
__global__ void __launch_bounds__(256) elemwise_kernel(
    const float* __restrict__ x, const float* __restrict__ xt1,
    const float* __restrict__ xt2, const float* __restrict__ xt3,
    const float* __restrict__ bu, const float* __restrict__ td) {
    const int warp = threadIdx.x >> 5, lane = threadIdx.x & 31;
    const size_t base = ((size_t)blockIdx.x * 8 + warp) * D;
    const float INV_SQRT2 = 0.70710678118654752440f;
    const float INV_SQRT2PI = 0.39894228040143267794f;

    float v[16], m[16];
#pragma unroll
    for (int j = 0; j < 16; j++) v[j] = x[base + lane + 32 * j];
    kwta_reg(v, m);
#pragma unroll
    for (int j = 0; j < 16; j++) {
        size_t idx = base + lane + 32 * j;
        float val = v[j];
        float cdf = 0.5f * (1.0f + erff(val * INV_SQRT2));
        float pdf = __expf(-0.5f * val * val) * INV_SQRT2PI;
        g_phix[idx] = __float2bfloat16(val * cdf * m[j]);
        g_phid[idx] = __float2bfloat16((cdf + val * pdf) * m[j]);
        g_bub[idx]  = __float2bfloat16(bu[idx]);
        float sgn = (val > 0.0f) ? 1.0f : ((val < 0.0f) ? -1.0f : 0.0f);
        g_tdx[idx]  = __float2bfloat16(3.0f * td[idx] - 5.5f * val - 1e-6f * sgn);
    }
    float c[16];
#pragma unroll
    for (int j = 0; j < 16; j++) {
        size_t idx = base + lane + 32 * j;
        c[j] = 0.5f * xt1[idx] + 0.3f * xt2[idx] + 0.2f * xt3[idx];
    }
    kwta_reg(c, m);
#pragma unroll
    for (int j = 0; j < 16; j++) {
        size_t idx = base + lane + 32 * j;
        float val = c[j];
        g_ctx[idx] = __float2bfloat16(val);
        float cdf = 0.5f * (1.0f + erff(val * INV_SQRT2));
        g_phic[idx] = __float2bfloat16(val * cdf * m[j]);
    }
}

// ---------------- cp.async helpers ----------------
__device__ __forceinline__ void cp16(void* s, const void* g) {
    unsigned sa = (unsigned)__cvta_generic_to_shared(s);
    asm volatile("cp.async.cg.shared.global [%0], [%1], 16;" :: "r"(sa), "l"(g));
}

// one BK=32 stage; concat jobs (nk=32) switch source at ks>=16
__device__ __forceinline__ void load_stage(__nv_bfloat16* stage,
                                           const __nv_bfloat16* A0, const __nv_bfloat16* B0,
                                           const __nv_bfloat16* A1, const __nv_bfloat16* B1,
                                           int ks, int tid) {
    const __nv_bfloat16* Ag = (ks >= 16) ? A1 : A0;
    const __nv_bfloat16* Bg = (ks >= 16) ? B1 : B0;
    int k0 = (ks & 15) * BK;
    __nv_bfloat16* As = stage;
    __nv_bfloat16* Bs = stage + BM * LDAS;
#pragma unroll
    for (int t = 0; t < 2; t++) {
        int task = tid + t * 256;
        int arow = task >> 2, ach = task & 3;
        cp16(As + arow * LDAS + ach * 8, Ag + (size_t)arow * D + k0 + ach * 8);
        int brow = task >> 4, bch = task & 15;
        cp16(Bs + brow * LDBS + bch * 8, Bg + (size_t)(k0 + brow) * D + bch * 8);
    }
}

// ---------------- single parallel GEMM phase ----------------
// mode 0: fb   = bub@W^T - phix@WWT - c        (K=1024 concat) -> bf16
// mode 1: P1   = phix@L + bub@(1.5V) + 1.5 b_in + tdx (K=1024) -> bf16
// mode 2: gate = sigmoid(ctx@Rg)                               -> bf16
// mode 3: rec  = phic@R                                        -> bf16
__global__ void __launch_bounds__(256) gemm_kernel(const float* __restrict__ b_in) {
    extern __shared__ unsigned char smem_raw[];
    __nv_bfloat16* smem = (__nv_bfloat16*)smem_raw;

    const int tid = threadIdx.x, wid = tid >> 5;
    const int wm = wid >> 2, wn = wid & 3;
    const int mode = blockIdx.z;
    const int n0 = blockIdx.x * BN, m0 = blockIdx.y * BM;

    const __nv_bfloat16 *A0, *B0, *A1 = 0, *B1 = 0;
    int nk = 16;
    switch (mode) {
        case 0: A0 = g_bub;  B0 = g_WTb; A1 = g_phix; B1 = g_nWWT; nk = 32; break;
        case 1: A0 = g_phix; B0 = g_Lb;  A1 = g_bub;  B1 = g_V15b; nk = 32; break;
        case 2: A0 = g_ctx;  B0 = g_Rgb; break;
        default: A0 = g_phic; B0 = g_Rb; break;
    }
    A0 += (size_t)m0 * D; B0 += n0;
    if (A1) { A1 += (size_t)m0 * D; B1 += n0; }

    wmma::fragment<wmma::accumulator, 16, 16, 16, float> acc[4][2];
#pragma unroll
    for (int i = 0; i < 4; i++)
#pragma unroll
        for (int j = 0; j < 2; j++) wmma::fill_fragment(acc[i][j], 0.0f);

    load_stage(smem + 0 * STAGE_E, A0, B0, A1, B1, 0, tid);
    asm volatile("cp.async.commit_group;" ::: "memory");
    load_stage(smem + 1 * STAGE_E, A0, B0, A1, B1, 1, tid);
    asm volatile("cp.async.commit_group;" ::: "memory");

    for (int ki = 0; ki < nk; ki++) {
        asm volatile("cp.async.wait_group 1;" ::: "memory");
        __syncthreads();
        __nv_bfloat16* As = smem + (ki % 3) * STAGE_E;
        __nv_bfloat16* Bs = As + BM * LDAS;
#pragma unroll
        for (int kk = 0; kk < BK; kk += 16) {
            wmma::fragment<wmma::matrix_a, 16, 16, 16, __nv_bfloat16, wmma::row_major> af[4];
            wmma::fragment<wmma::matrix_b, 16, 16, 16, __nv_bfloat16, wmma::row_major> bf_[2];
#pragma unroll
            for (int i = 0; i < 4; i++)
                wmma::load_matrix_sync(af[i], As + (wm * 64 + i * 16) * LDAS + kk, LDAS);
#pragma unroll
            for (int j = 0; j < 2; j++)
                wmma::load_matrix_sync(bf_[j], Bs + kk * LDBS + wn * 32 + j * 16, LDBS);
#pragma unroll
            for (int i = 0; i < 4; i++)
#pragma unroll
                for (int j = 0; j < 2; j++)
                    wmma::mma_sync(acc[i][j], af[i], bf_[j], acc[i][j]);
        }
        if (ki + 2 < nk) load_stage(smem + ((ki + 2) % 3) * STAGE_E, A0, B0, A1, B1, ki + 2, tid);
        asm volatile("cp.async.commit_group;" ::: "memory");
    }
    asm volatile("cp.async.wait_group 0;" ::: "memory");

    float* Es = (float*)smem_raw;
#pragma unroll 1
    for (int half = 0; half < 2; half++) {
        __syncthreads();
        if (wm == half)
#pragma unroll
            for (int i = 0; i < 4; i++)
#pragma unroll
                for (int j = 0; j < 2; j++)
                    wmma::store_matrix_sync(Es + (i * 16) * LDE + wn * 32 + j * 16,
                                            acc[i][j], LDE, wmma::mem_row_major);
        __syncthreads();
#pragma unroll 4
        for (int t = 0; t < 32; t++) {
            int idx = t * 256 + tid;
            int r = idx >> 7, c = idx & 127;
            int gc = n0 + c;
            size_t gi = (size_t)(m0 + half * 64 + r) * D + gc;
            float v = Es[r * LDE + c];
            switch (mode) {
                case 0: g_fb[gi] = __float2bfloat16(v - g_cvec[gc]); break;
                case 1:
                    g_P1[gi] = __float2bfloat16(v + 1.5f * b_in[gc] + __bfloat162float(g_tdx[gi]));
                    break;
                case 2: g_gate[gi] = __float2bfloat16(1.0f / (1.0f + __expf(-v))); break;
                default: g_rec[gi] = __float2bfloat16(v); break;
            }
        }
    }
}

// ---------------- g = fb*phid + P1 + rec*gate (+ partial sumsq) ------------
__global__ void __launch_bounds__(256) gfuse_kernel() {
    __shared__ float red[256];
    const int tid = threadIdx.x;
    const int base = blockIdx.x * 2048;          // bf162 units
    const __nv_bfloat162* fb2 = (const __nv_bfloat162*)g_fb;
    const __nv_bfloat162* pd2 = (const __nv_bfloat162*)g_phid;
    const __nv_bfloat162* p12 = (const __nv_bfloat162*)g_P1;
    const __nv_bfloat162* rc2 = (const __nv_bfloat162*)g_rec;
    const __nv_bfloat162* gt2 = (const __nv_bfloat162*)g_gate;
    __nv_bfloat162* gg2 = (__nv_bfloat162*)g_g;

    float ss = 0.0f;
#pragma unroll
    for (int t = 0; t < 8; t++) {
        int i = base + t * 256 + tid;
        float2 fb = __bfloat1622float2(fb2[i]);
        float2 pd = __bfloat1622float2(pd2[i]);
        float2 p1 = __bfloat1622float2(p12[i]);
        float2 rc = __bfloat1622float2(rc2[i]);
        float2 gt = __bfloat1622float2(gt2[i]);
        float gx = fb.x * pd.x + p1.x + rc.x * gt.x;
        float gy = fb.y * pd.y + p1.y + rc.y * gt.y;
        gg2[i] = __floats2bfloat162_rn(gx, gy);
        ss += gx * gx + gy * gy;
    }
    red[tid] = ss;
    __syncthreads();
    for (int o = 128; o > 0; o >>= 1) {
        if (tid < o) red[tid] += red[tid + o];
        __syncthreads();
    }
    if (tid == 0) g_part[blockIdx.x] = red[0];
}

// ---------------- global norm -> clip scale ----------------
__global__ void reduce_scale_kernel(const int* __restrict__ step_i, int nparts) {
    __shared__ float red[256];
    float s = 0.0f;
    for (int i = threadIdx.x; i < nparts; i += 256) s += g_part[i];
    red[threadIdx.x] = s;
    __syncthreads();
    for (int o = 128; o > 0; o >>= 1) {
        if (threadIdx.x < o) red[threadIdx.x] += red[threadIdx.x + o];
        __syncthreads();
    }
    if (threadIdx.x == 0) {
        float eta = 0.8f / (1.0f + 0.1f * (float)step_i[0]);
        float cc = 0.5f * eta;                   // TAU * eta
        float n = cc * sqrtf(red[0]);
        float sc = (n > 1.0f) ? (1.0f / (n + 1e-8f)) : 1.0f;
        g_scalef = cc * sc;
    }
}

// ---------------- finalize: x_new = clip(x + g*scale, -5, 5) ----------------
__global__ void finalize_kernel(const float* __restrict__ x, float* __restrict__ out, int n2) {
    float f = g_scalef;
    const float2* x2 = (const float2*)x;
    const __nv_bfloat162* gg = (const __nv_bfloat162*)g_g;
    float2* o2 = (float2*)out;
    for (int i = blockIdx.x * blockDim.x + threadIdx.x; i < n2; i += gridDim.x * blockDim.x) {
        float2 xv = x2[i];
        float2 gv = __bfloat1622float2(gg[i]);
        float2 o;
        o.x = fminf(5.0f, fmaxf(-5.0f, xv.x + gv.x * f));
        o.y = fminf(5.0f, fmaxf(-5.0f, xv.y + gv.y * f));
        o2[i] = o;
    }
}

extern "C" void kernel_launch(void* const* d_in, const int* in_sizes, int n_in,
                              void* d_out, int out_size) {
    const float* bu    = (const float*)d_in[0];
    const float* td    = (const float*)d_in[1];
    const float* x     = (const float*)d_in[2];
    const float* xt1   = (const float*)d_in[3];
    const float* xt2   = (const float*)d_in[4];
    const float* xt3   = (const float*)d_in[5];
    const float* V     = (const float*)d_in[6];
    const float* b_in  = (const float*)d_in[7];
    const float* W     = (const float*)d_in[8];
    const float* b_out = (const float*)d_in[9];
    const float* R     = (const float*)d_in[10];
    const float* Rg    = (const float*)d_in[11];
    const float* L     = (const float*)d_in[12];
    const int*   step  = (const int*)d_in[13];

    int Btot = in_sizes[2] / D;
    if (Btot > MAXB) Btot = MAXB;
    int mtiles = Btot / BM;             // 64

    cudaFuncSetAttribute(gemm_kernel, cudaFuncAttributeMaxDynamicSharedMemorySize, SMEM_GEMM);

    convert_kernel<<<128, 256>>>(W, V, R, Rg, L);
    wwt_kernel<<<dim3(4, 4), 256>>>();
    cvec_kernel<<<8, 256>>>(W, b_out);
    elemwise_kernel<<<Btot / 8, 256>>>(x, xt1, xt2, xt3, bu, td);
    gemm_kernel<<<dim3(D / BN, mtiles, 4), 256, SMEM_GEMM>>>(b_in);
    gfuse_kernel<<<(Btot * D) / 4096, 256>>>();
    reduce_scale_kernel<<<1, 256>>>(step, (Btot * D) / 4096);
    finalize_kernel<<<1024, 256>>>(x, (float*)d_out, Btot * D / 2);
}

// round 9
// speedup vs baseline: 1.6468x; 1.0724x over previous
#include <cuda_runtime.h>
#include <cuda_bf16.h>
#include <mma.h>
#include <math.h>

using namespace nvcuda;

#define D      512
#define KWTA   128
#define MAXB   8192

// GEMM tiling
#define BM     128
#define BN     128
#define BK     32
#define LDAS   40
#define LDBS   136
#define LDE    132
#define STAGE_E (BM * LDAS + BK * LDBS)          // 9472 bf16 per stage
#define NSTAGE 4
#define SMEM_GEMM (NSTAGE * STAGE_E * 2)         // 75776 bytes

#define NPART  1024

// ---------------- device scratch ----------------
__device__ __nv_bfloat16 g_Wb[D * D];            // W [O][I] row-major
__device__ __nv_bfloat16 g_WTb[D * D];           // W^T
__device__ __nv_bfloat16 g_nWWT[D * D];          // -(W W^T)
__device__ __nv_bfloat16 g_V15b[D * D];          // 1.5 V
__device__ __nv_bfloat16 g_Rb[D * D];
__device__ __nv_bfloat16 g_Rgb[D * D];
__device__ __nv_bfloat16 g_Lb[D * D];
__device__ float g_cvec[D];                      // c[o] = sum_i b_out[i] W[o][i]

__device__ __nv_bfloat16 g_phix[MAXB * D];
__device__ __nv_bfloat16 g_bub[MAXB * D];
__device__ __nv_bfloat16 g_ctx[MAXB * D];
__device__ __nv_bfloat16 g_phic[MAXB * D];
__device__ __nv_bfloat16 g_phid[MAXB * D];
__device__ __nv_bfloat16 g_tdx[MAXB * D];        // 3 td - 5.5 x - 1e-6 sign(x)
__device__ __nv_bfloat16 g_fb[MAXB * D];
__device__ __nv_bfloat16 g_P1[MAXB * D];
__device__ __nv_bfloat16 g_gate[MAXB * D];
__device__ __nv_bfloat16 g_rec[MAXB * D];
__device__ __nv_bfloat16 g_g[MAXB * D];

__device__ float g_part[NPART];
__device__ float g_scalef;

__device__ __forceinline__ float fast_tanh(float x) {
    float y;
    asm("tanh.approx.f32 %0, %1;" : "=f"(y) : "f"(x));
    return y;
}

// ---------------- weight conversion ----------------
__global__ void convert_kernel(const float* __restrict__ W, const float* __restrict__ V,
                               const float* __restrict__ R, const float* __restrict__ Rg,
                               const float* __restrict__ L) {
    int n = D * D;
    for (int idx = blockIdx.x * blockDim.x + threadIdx.x; idx < n; idx += gridDim.x * blockDim.x) {
        int i = idx >> 9, j = idx & 511;
        float w = W[idx];
        g_Wb[idx]        = __float2bfloat16(w);
        g_WTb[j * D + i] = __float2bfloat16(w);
        g_V15b[idx]      = __float2bfloat16(1.5f * V[idx]);
        g_Rb[idx]        = __float2bfloat16(R[idx]);
        g_Rgb[idx]       = __float2bfloat16(Rg[idx]);
        g_Lb[idx]        = __float2bfloat16(L[idx]);
    }
}

// ---------------- WWT = -(W @ W^T) bf16, 512x512x512 ----------------
__global__ void __launch_bounds__(256) wwt_kernel() {
    __shared__ float Es[64 * LDE];
    const int tid = threadIdx.x, wid = tid >> 5;
    const int wm = wid >> 2, wn = wid & 3;
    const int m0 = blockIdx.y * BM, n0 = blockIdx.x * BN;

    wmma::fragment<wmma::accumulator, 16, 16, 16, float> acc[4][2];
#pragma unroll
    for (int i = 0; i < 4; i++)
#pragma unroll
        for (int j = 0; j < 2; j++) wmma::fill_fragment(acc[i][j], 0.0f);

    for (int k = 0; k < D; k += 16) {
        wmma::fragment<wmma::matrix_a, 16, 16, 16, __nv_bfloat16, wmma::row_major> af[4];
        wmma::fragment<wmma::matrix_b, 16, 16, 16, __nv_bfloat16, wmma::row_major> bf_[2];
#pragma unroll
        for (int i = 0; i < 4; i++)
            wmma::load_matrix_sync(af[i], g_Wb + (size_t)(m0 + wm * 64 + i * 16) * D + k, D);
#pragma unroll
        for (int j = 0; j < 2; j++)
            wmma::load_matrix_sync(bf_[j], g_WTb + (size_t)k * D + n0 + wn * 32 + j * 16, D);
#pragma unroll
        for (int i = 0; i < 4; i++)
#pragma unroll
            for (int j = 0; j < 2; j++)
                wmma::mma_sync(acc[i][j], af[i], bf_[j], acc[i][j]);
    }
#pragma unroll 1
    for (int half = 0; half < 2; half++) {
        __syncthreads();
        if (wm == half)
#pragma unroll
            for (int i = 0; i < 4; i++)
#pragma unroll
                for (int j = 0; j < 2; j++)
                    wmma::store_matrix_sync(Es + (i * 16) * LDE + wn * 32 + j * 16,
                                            acc[i][j], LDE, wmma::mem_row_major);
        __syncthreads();
#pragma unroll 4
        for (int t = 0; t < 32; t++) {
            int idx = t * 256 + tid;
            int r = idx >> 7, c = idx & 127;
            g_nWWT[(size_t)(m0 + half * 64 + r) * D + n0 + c] = __float2bfloat16(-Es[r * LDE + c]);
        }
    }
}

// ---------------- c[o] = sum_i b_out[i] * W[o][i] ----------------
__global__ void cvec_kernel(const float* __restrict__ W, const float* __restrict__ b_out) {
    int gw = (blockIdx.x * blockDim.x + threadIdx.x) >> 5;
    int lane = threadIdx.x & 31;
    int nw = (gridDim.x * blockDim.x) >> 5;
    for (int row = gw; row < D; row += nw) {
        float s = 0.0f;
        for (int j = 0; j < 16; j++) {
            int i = lane + 32 * j;
            s += b_out[i] * W[(size_t)row * D + i];
        }
#pragma unroll
        for (int o = 16; o > 0; o >>= 1) s += __shfl_xor_sync(0xffffffffu, s, o);
        if (lane == 0) g_cvec[row] = s;
    }
}

// ---------------- exact register k-WTA with early exit ----------------
__device__ __forceinline__ void kwta_reg(const float v[16], float m[16]) {
    int lane = threadIdx.x & 31;
    unsigned u[16];
#pragma unroll
    for (int j = 0; j < 16; j++) {
        unsigned b = __float_as_uint(v[j]);
        u[j] = (b & 0x80000000u) ? ~b : (b | 0x80000000u);
    }
    unsigned prefix = 0;
    int exact = 0;
#pragma unroll 1
    for (int bit = 31; bit >= 0; --bit) {
        unsigned probe = prefix | (1u << bit);
        int c = 0;
#pragma unroll
        for (int j = 0; j < 16; j++) c += (u[j] >= probe);
        c = __reduce_add_sync(0xffffffffu, c);
        if (c >= KWTA) {
            prefix = probe;
            if (c == KWTA) { exact = 1; break; }   // mask is exactly u >= prefix
        }
    }
    if (exact) {
#pragma unroll
        for (int j = 0; j < 16; j++) m[j] = (u[j] >= prefix) ? 1.0f : 0.0f;
        return;
    }
    // tie path: prefix == exact bit pattern of the k-th largest value
    int cg = 0;
#pragma unroll
    for (int j = 0; j < 16; j++) cg += (u[j] > prefix);
    cg = __reduce_add_sync(0xffffffffu, cg);
    int remk = KWTA - cg;
    unsigned lmask = (1u << lane) - 1u;
    int running = 0;
#pragma unroll
    for (int j = 0; j < 16; j++) {
        bool eq = (u[j] == prefix);
        unsigned beq = __ballot_sync(0xffffffffu, eq);
        bool inc = (u[j] > prefix) || (eq && (running + __popc(beq & lmask)) < remk);
        running += __popc(beq);
        m[j] = inc ? 1.0f : 0.0f;
    }
}

// ---------------- elementwise precompute (one warp per batch row) ----------
__global__ void __launch_bounds__(256) elemwise_kernel(
    const float* __restrict__ x, const float* __restrict__ xt1,
    const float* __restrict__ xt2, const float* __restrict__ xt3,
    const float* __restrict__ bu, const float* __restrict__ td) {
    const int warp = threadIdx.x >> 5, lane = threadIdx.x & 31;
    const size_t base = ((size_t)blockIdx.x * 8 + warp) * D;
    const float INV_SQRT2PI = 0.39894228040143267794f;
    const float GC0 = 0.79788456080286535588f;   // sqrt(2/pi)
    const float GC1 = 0.044715f;

    float v[16], m[16];
#pragma unroll
    for (int j = 0; j < 16; j++) v[j] = x[base + lane + 32 * j];
    kwta_reg(v, m);
#pragma unroll
    for (int j = 0; j < 16; j++) {
        size_t idx = base + lane + 32 * j;
        float val = v[j];
        float t = fast_tanh(GC0 * (val + GC1 * val * val * val));
        float cdf = 0.5f * (1.0f + t);
        float pdf = __expf(-0.5f * val * val) * INV_SQRT2PI;
        g_phix[idx] = __float2bfloat16(val * cdf * m[j]);
        g_phid[idx] = __float2bfloat16((cdf + val * pdf) * m[j]);
        g_bub[idx]  = __float2bfloat16(bu[idx]);
        float sgn = (val > 0.0f) ? 1.0f : ((val < 0.0f) ? -1.0f : 0.0f);
        g_tdx[idx]  = __float2bfloat16(3.0f * td[idx] - 5.5f * val - 1e-6f * sgn);
    }
    float c[16];
#pragma unroll
    for (int j = 0; j < 16; j++) {
        size_t idx = base + lane + 32 * j;
        c[j] = 0.5f * xt1[idx] + 0.3f * xt2[idx] + 0.2f * xt3[idx];
    }
    kwta_reg(c, m);
#pragma unroll
    for (int j = 0; j < 16; j++) {
        size_t idx = base + lane + 32 * j;
        float val = c[j];
        g_ctx[idx] = __float2bfloat16(val);
        float t = fast_tanh(GC0 * (val + GC1 * val * val * val));
        g_phic[idx] = __float2bfloat16(val * 0.5f * (1.0f + t) * m[j]);
    }
}

// ---------------- cp.async helpers ----------------
__device__ __forceinline__ void cp16(void* s, const void* g) {
    unsigned sa = (unsigned)__cvta_generic_to_shared(s);
    asm volatile("cp.async.cg.shared.global [%0], [%1], 16;" :: "r"(sa), "l"(g));
}

__device__ __forceinline__ void load_stage(__nv_bfloat16* stage,
                                           const __nv_bfloat16* A0, const __nv_bfloat16* B0,
                                           const __nv_bfloat16* A1, const __nv_bfloat16* B1,
                                           int ks, int tid) {
    const __nv_bfloat16* Ag = (ks >= 16) ? A1 : A0;
    const __nv_bfloat16* Bg = (ks >= 16) ? B1 : B0;
    int k0 = (ks & 15) * BK;
    __nv_bfloat16* As = stage;
    __nv_bfloat16* Bs = stage + BM * LDAS;
#pragma unroll
    for (int t = 0; t < 2; t++) {
        int task = tid + t * 256;
        int arow = task >> 2, ach = task & 3;
        cp16(As + arow * LDAS + ach * 8, Ag + (size_t)arow * D + k0 + ach * 8);
        int brow = task >> 4, bch = task & 15;
        cp16(Bs + brow * LDBS + bch * 8, Bg + (size_t)(k0 + brow) * D + bch * 8);
    }
}

// ---------------- single parallel GEMM phase ----------------
// mode 0: fb   = bub@W^T - phix@WWT - c        (K=1024 concat) -> bf16
// mode 1: P1   = phix@L + bub@(1.5V) + 1.5 b_in + tdx (K=1024) -> bf16
// mode 2: gate = sigmoid(ctx@Rg)                               -> bf16
// mode 3: rec  = phic@R                                        -> bf16
__global__ void __launch_bounds__(256) gemm_kernel(const float* __restrict__ b_in) {
    extern __shared__ unsigned char smem_raw[];
    __nv_bfloat16* smem = (__nv_bfloat16*)smem_raw;

    const int tid = threadIdx.x, wid = tid >> 5;
    const int wm = wid >> 2, wn = wid & 3;
    const int mode = blockIdx.z;
    const int n0 = blockIdx.x * BN, m0 = blockIdx.y * BM;

    const __nv_bfloat16 *A0, *B0, *A1 = 0, *B1 = 0;
    int nk = 16;
    switch (mode) {
        case 0: A0 = g_bub;  B0 = g_WTb; A1 = g_phix; B1 = g_nWWT; nk = 32; break;
        case 1: A0 = g_phix; B0 = g_Lb;  A1 = g_bub;  B1 = g_V15b; nk = 32; break;
        case 2: A0 = g_ctx;  B0 = g_Rgb; break;
        default: A0 = g_phic; B0 = g_Rb; break;
    }
    A0 += (size_t)m0 * D; B0 += n0;
    if (A1) { A1 += (size_t)m0 * D; B1 += n0; }

    wmma::fragment<wmma::accumulator, 16, 16, 16, float> acc[4][2];
#pragma unroll
    for (int i = 0; i < 4; i++)
#pragma unroll
        for (int j = 0; j < 2; j++) wmma::fill_fragment(acc[i][j], 0.0f);

    // 4-buffer pipeline, prefetch distance 3
    load_stage(smem + 0 * STAGE_E, A0, B0, A1, B1, 0, tid);
    asm volatile("cp.async.commit_group;" ::: "memory");
    load_stage(smem + 1 * STAGE_E, A0, B0, A1, B1, 1, tid);
    asm volatile("cp.async.commit_group;" ::: "memory");
    load_stage(smem + 2 * STAGE_E, A0, B0, A1, B1, 2, tid);
    asm volatile("cp.async.commit_group;" ::: "memory");

    for (int ki = 0; ki < nk; ki++) {
        asm volatile("cp.async.wait_group 2;" ::: "memory");
        __syncthreads();
        __nv_bfloat16* As = smem + (ki % NSTAGE) * STAGE_E;
        __nv_bfloat16* Bs = As + BM * LDAS;
#pragma unroll
        for (int kk = 0; kk < BK; kk += 16) {
            wmma::fragment<wmma::matrix_a, 16, 16, 16, __nv_bfloat16, wmma::row_major> af[4];
            wmma::fragment<wmma::matrix_b, 16, 16, 16, __nv_bfloat16, wmma::row_major> bf_[2];
#pragma unroll
            for (int i = 0; i < 4; i++)
                wmma::load_matrix_sync(af[i], As + (wm * 64 + i * 16) * LDAS + kk, LDAS);
#pragma unroll
            for (int j = 0; j < 2; j++)
                wmma::load_matrix_sync(bf_[j], Bs + kk * LDBS + wn * 32 + j * 16, LDBS);
#pragma unroll
            for (int i = 0; i < 4; i++)
#pragma unroll
                for (int j = 0; j < 2; j++)
                    wmma::mma_sync(acc[i][j], af[i], bf_[j], acc[i][j]);
        }
        if (ki + 3 < nk) load_stage(smem + ((ki + 3) % NSTAGE) * STAGE_E, A0, B0, A1, B1, ki + 3, tid);
        asm volatile("cp.async.commit_group;" ::: "memory");
    }
    asm volatile("cp.async.wait_group 0;" ::: "memory");

    float* Es = (float*)smem_raw;
#pragma unroll 1
    for (int half = 0; half < 2; half++) {
        __syncthreads();
        if (wm == half)
#pragma unroll
            for (int i = 0; i < 4; i++)
#pragma unroll
                for (int j = 0; j < 2; j++)
                    wmma::store_matrix_sync(Es + (i * 16) * LDE + wn * 32 + j * 16,
                                            acc[i][j], LDE, wmma::mem_row_major);
        __syncthreads();
#pragma unroll 4
        for (int t = 0; t < 32; t++) {
            int idx = t * 256 + tid;
            int r = idx >> 7, c = idx & 127;
            int gc = n0 + c;
            size_t gi = (size_t)(m0 + half * 64 + r) * D + gc;
            float v = Es[r * LDE + c];
            switch (mode) {
                case 0: g_fb[gi] = __float2bfloat16(v - g_cvec[gc]); break;
                case 1:
                    g_P1[gi] = __float2bfloat16(v + 1.5f * b_in[gc] + __bfloat162float(g_tdx[gi]));
                    break;
                case 2: g_gate[gi] = __float2bfloat16(1.0f / (1.0f + __expf(-v))); break;
                default: g_rec[gi] = __float2bfloat16(v); break;
            }
        }
    }
}

// ---------------- g = fb*phid + P1 + rec*gate (+ partial sumsq) ------------
__global__ void __launch_bounds__(256) gfuse_kernel() {
    __shared__ float red[256];
    const int tid = threadIdx.x;
    const int base = blockIdx.x * 2048;
    const __nv_bfloat162* fb2 = (const __nv_bfloat162*)g_fb;
    const __nv_bfloat162* pd2 = (const __nv_bfloat162*)g_phid;
    const __nv_bfloat162* p12 = (const __nv_bfloat162*)g_P1;
    const __nv_bfloat162* rc2 = (const __nv_bfloat162*)g_rec;
    const __nv_bfloat162* gt2 = (const __nv_bfloat162*)g_gate;
    __nv_bfloat162* gg2 = (__nv_bfloat162*)g_g;

    float ss = 0.0f;
#pragma unroll
    for (int t = 0; t < 8; t++) {
        int i = base + t * 256 + tid;
        float2 fb = __bfloat1622float2(fb2[i]);
        float2 pd = __bfloat1622float2(pd2[i]);
        float2 p1 = __bfloat1622float2(p12[i]);
        float2 rc = __bfloat1622float2(rc2[i]);
        float2 gt = __bfloat1622float2(gt2[i]);
        float gx = fb.x * pd.x + p1.x + rc.x * gt.x;
        float gy = fb.y * pd.y + p1.y + rc.y * gt.y;
        gg2[i] = __floats2bfloat162_rn(gx, gy);
        ss += gx * gx + gy * gy;
    }
    red[tid] = ss;
    __syncthreads();
    for (int o = 128; o > 0; o >>= 1) {
        if (tid < o) red[tid] += red[tid + o];
        __syncthreads();
    }
    if (tid == 0) g_part[blockIdx.x] = red[0];
}

// ---------------- global norm -> clip scale ----------------
__global__ void reduce_scale_kernel(const int* __restrict__ step_i, int nparts) {
    __shared__ float red[256];
    float s = 0.0f;
    for (int i = threadIdx.x; i < nparts; i += 256) s += g_part[i];
    red[threadIdx.x] = s;
    __syncthreads();
    for (int o = 128; o > 0; o >>= 1) {
        if (threadIdx.x < o) red[threadIdx.x] += red[threadIdx.x + o];
        __syncthreads();
    }
    if (threadIdx.x == 0) {
        float eta = 0.8f / (1.0f + 0.1f * (float)step_i[0]);
        float cc = 0.5f * eta;                   // TAU * eta
        float n = cc * sqrtf(red[0]);
        float sc = (n > 1.0f) ? (1.0f / (n + 1e-8f)) : 1.0f;
        g_scalef = cc * sc;
    }
}

// ---------------- finalize: x_new = clip(x + g*scale, -5, 5) ----------------
__global__ void finalize_kernel(const float* __restrict__ x, float* __restrict__ out, int n2) {
    float f = g_scalef;
    const float2* x2 = (const float2*)x;
    const __nv_bfloat162* gg = (const __nv_bfloat162*)g_g;
    float2* o2 = (float2*)out;
    for (int i = blockIdx.x * blockDim.x + threadIdx.x; i < n2; i += gridDim.x * blockDim.x) {
        float2 xv = x2[i];
        float2 gv = __bfloat1622float2(gg[i]);
        float2 o;
        o.x = fminf(5.0f, fmaxf(-5.0f, xv.x + gv.x * f));
        o.y = fminf(5.0f, fmaxf(-5.0f, xv.y + gv.y * f));
        o2[i] = o;
    }
}

extern "C" void kernel_launch(void* const* d_in, const int* in_sizes, int n_in,
                              void* d_out, int out_size) {
    const float* bu    = (const float*)d_in[0];
    const float* td    = (const float*)d_in[1];
    const float* x     = (const float*)d_in[2];
    const float* xt1   = (const float*)d_in[3];
    const float* xt2   = (const float*)d_in[4];
    const float* xt3   = (const float*)d_in[5];
    const float* V     = (const float*)d_in[6];
    const float* b_in  = (const float*)d_in[7];
    const float* W     = (const float*)d_in[8];
    const float* b_out = (const float*)d_in[9];
    const float* R     = (const float*)d_in[10];
    const float* Rg    = (const float*)d_in[11];
    const float* L     = (const float*)d_in[12];
    const int*   step  = (const int*)d_in[13];

    int Btot = in_sizes[2] / D;
    if (Btot > MAXB) Btot = MAXB;
    int mtiles = Btot / BM;             // 64

    cudaFuncSetAttribute(gemm_kernel, cudaFuncAttributeMaxDynamicSharedMemorySize, SMEM_GEMM);

    convert_kernel<<<128, 256>>>(W, V, R, Rg, L);
    wwt_kernel<<<dim3(4, 4), 256>>>();
    cvec_kernel<<<8, 256>>>(W, b_out);
    elemwise_kernel<<<Btot / 8, 256>>>(x, xt1, xt2, xt3, bu, td);
    gemm_kernel<<<dim3(D / BN, mtiles, 4), 256, SMEM_GEMM>>>(b_in);
    gfuse_kernel<<<(Btot * D) / 4096, 256>>>();
    reduce_scale_kernel<<<1, 256>>>(step, (Btot * D) / 4096);
    finalize_kernel<<<1024, 256>>>(x, (float*)d_out, Btot * D / 2);
}

// round 10
// speedup vs baseline: 1.7050x; 1.0353x over previous
#include <cuda_runtime.h>
#include <cuda_bf16.h>
#include <mma.h>
#include <math.h>

using namespace nvcuda;

#define D      512
#define KWTA   128
#define MAXB   8192

// GEMM tiling (2 CTAs/SM: 56.8KB smem, <=128 regs enforced)
#define BM     128
#define BN     128
#define BK     32
#define LDAS   40
#define LDBS   136
#define LDE    132
#define STAGE_E (BM * LDAS + BK * LDBS)          // 9472 bf16 per stage
#define NSTAGE 3
#define SMEM_GEMM (NSTAGE * STAGE_E * 2)         // 56832 bytes

#define NPART  1024

// ---------------- device scratch ----------------
__device__ __nv_bfloat16 g_Wb[D * D];            // W [O][I] row-major
__device__ __nv_bfloat16 g_WTb[D * D];           // W^T
__device__ __nv_bfloat16 g_nWWT[D * D];          // -(W W^T)
__device__ __nv_bfloat16 g_V15b[D * D];          // 1.5 V
__device__ __nv_bfloat16 g_Rb[D * D];
__device__ __nv_bfloat16 g_Rgb[D * D];
__device__ __nv_bfloat16 g_Lb[D * D];
__device__ float g_cvec[D];                      // c[o] = sum_i b_out[i] W[o][i]

__device__ __nv_bfloat16 g_phix[MAXB * D];
__device__ __nv_bfloat16 g_bub[MAXB * D];
__device__ __nv_bfloat16 g_ctx[MAXB * D];
__device__ __nv_bfloat16 g_phic[MAXB * D];
__device__ __nv_bfloat16 g_phid[MAXB * D];
__device__ __nv_bfloat16 g_tdx[MAXB * D];        // 3 td - 5.5 x - 1e-6 sign(x)
__device__ __nv_bfloat16 g_fb[MAXB * D];
__device__ __nv_bfloat16 g_P1[MAXB * D];
__device__ __nv_bfloat16 g_gate[MAXB * D];
__device__ __nv_bfloat16 g_rec[MAXB * D];
__device__ __nv_bfloat16 g_g[MAXB * D];

__device__ float g_part[NPART];
__device__ float g_scalef;

__device__ __forceinline__ float fast_tanh(float x) {
    float y;
    asm("tanh.approx.f32 %0, %1;" : "=f"(y) : "f"(x));
    return y;
}

// ---------------- weight conversion ----------------
__global__ void convert_kernel(const float* __restrict__ W, const float* __restrict__ V,
                               const float* __restrict__ R, const float* __restrict__ Rg,
                               const float* __restrict__ L) {
    int n = D * D;
    for (int idx = blockIdx.x * blockDim.x + threadIdx.x; idx < n; idx += gridDim.x * blockDim.x) {
        int i = idx >> 9, j = idx & 511;
        float w = W[idx];
        g_Wb[idx]        = __float2bfloat16(w);
        g_WTb[j * D + i] = __float2bfloat16(w);
        g_V15b[idx]      = __float2bfloat16(1.5f * V[idx]);
        g_Rb[idx]        = __float2bfloat16(R[idx]);
        g_Rgb[idx]       = __float2bfloat16(Rg[idx]);
        g_Lb[idx]        = __float2bfloat16(L[idx]);
    }
}

// ---------------- WWT = -(W @ W^T) bf16, 512x512x512 ----------------
__global__ void __launch_bounds__(256) wwt_kernel() {
    __shared__ float Es[64 * LDE];
    const int tid = threadIdx.x, wid = tid >> 5;
    const int wm = wid >> 2, wn = wid & 3;
    const int m0 = blockIdx.y * BM, n0 = blockIdx.x * BN;

    wmma::fragment<wmma::accumulator, 16, 16, 16, float> acc[4][2];
#pragma unroll
    for (int i = 0; i < 4; i++)
#pragma unroll
        for (int j = 0; j < 2; j++) wmma::fill_fragment(acc[i][j], 0.0f);

    for (int k = 0; k < D; k += 16) {
        wmma::fragment<wmma::matrix_a, 16, 16, 16, __nv_bfloat16, wmma::row_major> af[4];
        wmma::fragment<wmma::matrix_b, 16, 16, 16, __nv_bfloat16, wmma::row_major> bf_[2];
#pragma unroll
        for (int i = 0; i < 4; i++)
            wmma::load_matrix_sync(af[i], g_Wb + (size_t)(m0 + wm * 64 + i * 16) * D + k, D);
#pragma unroll
        for (int j = 0; j < 2; j++)
            wmma::load_matrix_sync(bf_[j], g_WTb + (size_t)k * D + n0 + wn * 32 + j * 16, D);
#pragma unroll
        for (int i = 0; i < 4; i++)
#pragma unroll
            for (int j = 0; j < 2; j++)
                wmma::mma_sync(acc[i][j], af[i], bf_[j], acc[i][j]);
    }
#pragma unroll 1
    for (int half = 0; half < 2; half++) {
        __syncthreads();
        if (wm == half)
#pragma unroll
            for (int i = 0; i < 4; i++)
#pragma unroll
                for (int j = 0; j < 2; j++)
                    wmma::store_matrix_sync(Es + (i * 16) * LDE + wn * 32 + j * 16,
                                            acc[i][j], LDE, wmma::mem_row_major);
        __syncthreads();
#pragma unroll 4
        for (int t = 0; t < 32; t++) {
            int idx = t * 256 + tid;
            int r = idx >> 7, c = idx & 127;
            g_nWWT[(size_t)(m0 + half * 64 + r) * D + n0 + c] = __float2bfloat16(-Es[r * LDE + c]);
        }
    }
}

// ---------------- c[o] = sum_i b_out[i] * W[o][i] ----------------
__global__ void cvec_kernel(const float* __restrict__ W, const float* __restrict__ b_out) {
    int gw = (blockIdx.x * blockDim.x + threadIdx.x) >> 5;
    int lane = threadIdx.x & 31;
    int nw = (gridDim.x * blockDim.x) >> 5;
    for (int row = gw; row < D; row += nw) {
        float s = 0.0f;
        for (int j = 0; j < 16; j++) {
            int i = lane + 32 * j;
            s += b_out[i] * W[(size_t)row * D + i];
        }
#pragma unroll
        for (int o = 16; o > 0; o >>= 1) s += __shfl_xor_sync(0xffffffffu, s, o);
        if (lane == 0) g_cvec[row] = s;
    }
}

// ---------------- exact register k-WTA with early exit ----------------
__device__ __forceinline__ void kwta_reg(const float v[16], float m[16]) {
    int lane = threadIdx.x & 31;
    unsigned u[16];
#pragma unroll
    for (int j = 0; j < 16; j++) {
        unsigned b = __float_as_uint(v[j]);
        u[j] = (b & 0x80000000u) ? ~b : (b | 0x80000000u);
    }
    unsigned prefix = 0;
    int exact = 0;
#pragma unroll 1
    for (int bit = 31; bit >= 0; --bit) {
        unsigned probe = prefix | (1u << bit);
        int c = 0;
#pragma unroll
        for (int j = 0; j < 16; j++) c += (u[j] >= probe);
        c = __reduce_add_sync(0xffffffffu, c);
        if (c >= KWTA) {
            prefix = probe;
            if (c == KWTA) { exact = 1; break; }   // mask is exactly u >= prefix
        }
    }
    if (exact) {
#pragma unroll
        for (int j = 0; j < 16; j++) m[j] = (u[j] >= prefix) ? 1.0f : 0.0f;
        return;
    }
    // tie path: prefix == exact bit pattern of the k-th largest value
    int cg = 0;
#pragma unroll
    for (int j = 0; j < 16; j++) cg += (u[j] > prefix);
    cg = __reduce_add_sync(0xffffffffu, cg);
    int remk = KWTA - cg;
    unsigned lmask = (1u << lane) - 1u;
    int running = 0;
#pragma unroll
    for (int j = 0; j < 16; j++) {
        bool eq = (u[j] == prefix);
        unsigned beq = __ballot_sync(0xffffffffu, eq);
        bool inc = (u[j] > prefix) || (eq && (running + __popc(beq & lmask)) < remk);
        running += __popc(beq);
        m[j] = inc ? 1.0f : 0.0f;
    }
}

// ---------------- elementwise precompute (one warp per batch row) ----------
__global__ void __launch_bounds__(256) elemwise_kernel(
    const float* __restrict__ x, const float* __restrict__ xt1,
    const float* __restrict__ xt2, const float* __restrict__ xt3,
    const float* __restrict__ bu, const float* __restrict__ td) {
    const int warp = threadIdx.x >> 5, lane = threadIdx.x & 31;
    const size_t base = ((size_t)blockIdx.x * 8 + warp) * D;
    const float INV_SQRT2PI = 0.39894228040143267794f;
    const float GC0 = 0.79788456080286535588f;   // sqrt(2/pi)
    const float GC1 = 0.044715f;

    float v[16], m[16];
#pragma unroll
    for (int j = 0; j < 16; j++) v[j] = x[base + lane + 32 * j];
    kwta_reg(v, m);
#pragma unroll
    for (int j = 0; j < 16; j++) {
        size_t idx = base + lane + 32 * j;
        float val = v[j];
        float t = fast_tanh(GC0 * (val + GC1 * val * val * val));
        float cdf = 0.5f * (1.0f + t);
        float pdf = __expf(-0.5f * val * val) * INV_SQRT2PI;
        g_phix[idx] = __float2bfloat16(val * cdf * m[j]);
        g_phid[idx] = __float2bfloat16((cdf + val * pdf) * m[j]);
        g_bub[idx]  = __float2bfloat16(bu[idx]);
        float sgn = (val > 0.0f) ? 1.0f : ((val < 0.0f) ? -1.0f : 0.0f);
        g_tdx[idx]  = __float2bfloat16(3.0f * td[idx] - 5.5f * val - 1e-6f * sgn);
    }
    float c[16];
#pragma unroll
    for (int j = 0; j < 16; j++) {
        size_t idx = base + lane + 32 * j;
        c[j] = 0.5f * xt1[idx] + 0.3f * xt2[idx] + 0.2f * xt3[idx];
    }
    kwta_reg(c, m);
#pragma unroll
    for (int j = 0; j < 16; j++) {
        size_t idx = base + lane + 32 * j;
        float val = c[j];
        g_ctx[idx] = __float2bfloat16(val);
        float t = fast_tanh(GC0 * (val + GC1 * val * val * val));
        g_phic[idx] = __float2bfloat16(val * 0.5f * (1.0f + t) * m[j]);
    }
}

// ---------------- cp.async helpers ----------------
__device__ __forceinline__ void cp16(void* s, const void* g) {
    unsigned sa = (unsigned)__cvta_generic_to_shared(s);
    asm volatile("cp.async.cg.shared.global [%0], [%1], 16;" :: "r"(sa), "l"(g));
}

__device__ __forceinline__ void load_stage(__nv_bfloat16* stage,
                                           const __nv_bfloat16* A0, const __nv_bfloat16* B0,
                                           const __nv_bfloat16* A1, const __nv_bfloat16* B1,
                                           int ks, int tid) {
    const __nv_bfloat16* Ag = (ks >= 16) ? A1 : A0;
    const __nv_bfloat16* Bg = (ks >= 16) ? B1 : B0;
    int k0 = (ks & 15) * BK;
    __nv_bfloat16* As = stage;
    __nv_bfloat16* Bs = stage + BM * LDAS;
#pragma unroll
    for (int t = 0; t < 2; t++) {
        int task = tid + t * 256;
        int arow = task >> 2, ach = task & 3;
        cp16(As + arow * LDAS + ach * 8, Ag + (size_t)arow * D + k0 + ach * 8);
        int brow = task >> 4, bch = task & 15;
        cp16(Bs + brow * LDBS + bch * 8, Bg + (size_t)(k0 + brow) * D + bch * 8);
    }
}

// ---------------- single parallel GEMM phase ----------------
// mode 0: fb   = bub@W^T - phix@WWT - c        (K=1024 concat) -> bf16
// mode 1: P1   = phix@L + bub@(1.5V) + 1.5 b_in + tdx (K=1024) -> bf16
// mode 2: gate = sigmoid(ctx@Rg)                               -> bf16
// mode 3: rec  = phic@R                                        -> bf16
__global__ void __launch_bounds__(256, 2) gemm_kernel(const float* __restrict__ b_in) {
    extern __shared__ unsigned char smem_raw[];
    __nv_bfloat16* smem = (__nv_bfloat16*)smem_raw;

    const int tid = threadIdx.x, wid = tid >> 5;
    const int wm = wid >> 2, wn = wid & 3;
    const int mode = blockIdx.z;
    const int n0 = blockIdx.x * BN, m0 = blockIdx.y * BM;

    const __nv_bfloat16 *A0, *B0, *A1 = 0, *B1 = 0;
    int nk = 16;
    switch (mode) {
        case 0: A0 = g_bub;  B0 = g_WTb; A1 = g_phix; B1 = g_nWWT; nk = 32; break;
        case 1: A0 = g_phix; B0 = g_Lb;  A1 = g_bub;  B1 = g_V15b; nk = 32; break;
        case 2: A0 = g_ctx;  B0 = g_Rgb; break;
        default: A0 = g_phic; B0 = g_Rb; break;
    }
    A0 += (size_t)m0 * D; B0 += n0;
    if (A1) { A1 += (size_t)m0 * D; B1 += n0; }

    wmma::fragment<wmma::accumulator, 16, 16, 16, float> acc[4][2];
#pragma unroll
    for (int i = 0; i < 4; i++)
#pragma unroll
        for (int j = 0; j < 2; j++) wmma::fill_fragment(acc[i][j], 0.0f);

    load_stage(smem + 0 * STAGE_E, A0, B0, A1, B1, 0, tid);
    asm volatile("cp.async.commit_group;" ::: "memory");
    load_stage(smem + 1 * STAGE_E, A0, B0, A1, B1, 1, tid);
    asm volatile("cp.async.commit_group;" ::: "memory");

    for (int ki = 0; ki < nk; ki++) {
        asm volatile("cp.async.wait_group 1;" ::: "memory");
        __syncthreads();
        __nv_bfloat16* As = smem + (ki % NSTAGE) * STAGE_E;
        __nv_bfloat16* Bs = As + BM * LDAS;
#pragma unroll
        for (int kk = 0; kk < BK; kk += 16) {
            wmma::fragment<wmma::matrix_a, 16, 16, 16, __nv_bfloat16, wmma::row_major> af[4];
            wmma::fragment<wmma::matrix_b, 16, 16, 16, __nv_bfloat16, wmma::row_major> bf_[2];
#pragma unroll
            for (int i = 0; i < 4; i++)
                wmma::load_matrix_sync(af[i], As + (wm * 64 + i * 16) * LDAS + kk, LDAS);
#pragma unroll
            for (int j = 0; j < 2; j++)
                wmma::load_matrix_sync(bf_[j], Bs + kk * LDBS + wn * 32 + j * 16, LDBS);
#pragma unroll
            for (int i = 0; i < 4; i++)
#pragma unroll
                for (int j = 0; j < 2; j++)
                    wmma::mma_sync(acc[i][j], af[i], bf_[j], acc[i][j]);
        }
        if (ki + 2 < nk) load_stage(smem + ((ki + 2) % NSTAGE) * STAGE_E, A0, B0, A1, B1, ki + 2, tid);
        asm volatile("cp.async.commit_group;" ::: "memory");
    }
    asm volatile("cp.async.wait_group 0;" ::: "memory");

    float* Es = (float*)smem_raw;
#pragma unroll 1
    for (int half = 0; half < 2; half++) {
        __syncthreads();
        if (wm == half)
#pragma unroll
            for (int i = 0; i < 4; i++)
#pragma unroll
                for (int j = 0; j < 2; j++)
                    wmma::store_matrix_sync(Es + (i * 16) * LDE + wn * 32 + j * 16,
                                            acc[i][j], LDE, wmma::mem_row_major);
        __syncthreads();
#pragma unroll 4
        for (int t = 0; t < 32; t++) {
            int idx = t * 256 + tid;
            int r = idx >> 7, c = idx & 127;
            int gc = n0 + c;
            size_t gi = (size_t)(m0 + half * 64 + r) * D + gc;
            float v = Es[r * LDE + c];
            switch (mode) {
                case 0: g_fb[gi] = __float2bfloat16(v - g_cvec[gc]); break;
                case 1:
                    g_P1[gi] = __float2bfloat16(v + 1.5f * b_in[gc] + __bfloat162float(g_tdx[gi]));
                    break;
                case 2: g_gate[gi] = __float2bfloat16(1.0f / (1.0f + __expf(-v))); break;
                default: g_rec[gi] = __float2bfloat16(v); break;
            }
        }
    }
}

// ---------------- g = fb*phid + P1 + rec*gate (+ partial sumsq) ------------
__global__ void __launch_bounds__(256) gfuse_kernel() {
    __shared__ float red[256];
    const int tid = threadIdx.x;
    const int base = blockIdx.x * 2048;
    const __nv_bfloat162* fb2 = (const __nv_bfloat162*)g_fb;
    const __nv_bfloat162* pd2 = (const __nv_bfloat162*)g_phid;
    const __nv_bfloat162* p12 = (const __nv_bfloat162*)g_P1;
    const __nv_bfloat162* rc2 = (const __nv_bfloat162*)g_rec;
    const __nv_bfloat162* gt2 = (const __nv_bfloat162*)g_gate;
    __nv_bfloat162* gg2 = (__nv_bfloat162*)g_g;

    float ss = 0.0f;
#pragma unroll
    for (int t = 0; t < 8; t++) {
        int i = base + t * 256 + tid;
        float2 fb = __bfloat1622float2(fb2[i]);
        float2 pd = __bfloat1622float2(pd2[i]);
        float2 p1 = __bfloat1622float2(p12[i]);
        float2 rc = __bfloat1622float2(rc2[i]);
        float2 gt = __bfloat1622float2(gt2[i]);
        float gx = fb.x * pd.x + p1.x + rc.x * gt.x;
        float gy = fb.y * pd.y + p1.y + rc.y * gt.y;
        gg2[i] = __floats2bfloat162_rn(gx, gy);
        ss += gx * gx + gy * gy;
    }
    red[tid] = ss;
    __syncthreads();
    for (int o = 128; o > 0; o >>= 1) {
        if (tid < o) red[tid] += red[tid + o];
        __syncthreads();
    }
    if (tid == 0) g_part[blockIdx.x] = red[0];
}

// ---------------- global norm -> clip scale ----------------
__global__ void reduce_scale_kernel(const int* __restrict__ step_i, int nparts) {
    __shared__ float red[256];
    float s = 0.0f;
    for (int i = threadIdx.x; i < nparts; i += 256) s += g_part[i];
    red[threadIdx.x] = s;
    __syncthreads();
    for (int o = 128; o > 0; o >>= 1) {
        if (threadIdx.x < o) red[threadIdx.x] += red[threadIdx.x + o];
        __syncthreads();
    }
    if (threadIdx.x == 0) {
        float eta = 0.8f / (1.0f + 0.1f * (float)step_i[0]);
        float cc = 0.5f * eta;                   // TAU * eta
        float n = cc * sqrtf(red[0]);
        float sc = (n > 1.0f) ? (1.0f / (n + 1e-8f)) : 1.0f;
        g_scalef = cc * sc;
    }
}

// ---------------- finalize: x_new = clip(x + g*scale, -5, 5) ----------------
__global__ void finalize_kernel(const float* __restrict__ x, float* __restrict__ out, int n4) {
    float f = g_scalef;
    const float4* x4 = (const float4*)x;
    const float2* gg = (const float2*)g_g;       // 4 bf16 per float2
    float4* o4 = (float4*)out;
    for (int i = blockIdx.x * blockDim.x + threadIdx.x; i < n4; i += gridDim.x * blockDim.x) {
        float4 xv = x4[i];
        float2 gpack = gg[i];
        __nv_bfloat162 glo = *reinterpret_cast<__nv_bfloat162*>(&gpack.x);
        __nv_bfloat162 ghi = *reinterpret_cast<__nv_bfloat162*>(&gpack.y);
        float2 g0 = __bfloat1622float2(glo);
        float2 g1 = __bfloat1622float2(ghi);
        float4 o;
        o.x = fminf(5.0f, fmaxf(-5.0f, xv.x + g0.x * f));
        o.y = fminf(5.0f, fmaxf(-5.0f, xv.y + g0.y * f));
        o.z = fminf(5.0f, fmaxf(-5.0f, xv.z + g1.x * f));
        o.w = fminf(5.0f, fmaxf(-5.0f, xv.w + g1.y * f));
        o4[i] = o;
    }
}

extern "C" void kernel_launch(void* const* d_in, const int* in_sizes, int n_in,
                              void* d_out, int out_size) {
    const float* bu    = (const float*)d_in[0];
    const float* td    = (const float*)d_in[1];
    const float* x     = (const float*)d_in[2];
    const float* xt1   = (const float*)d_in[3];
    const float* xt2   = (const float*)d_in[4];
    const float* xt3   = (const float*)d_in[5];
    const float* V     = (const float*)d_in[6];
    const float* b_in  = (const float*)d_in[7];
    const float* W     = (const float*)d_in[8];
    const float* b_out = (const float*)d_in[9];
    const float* R     = (const float*)d_in[10];
    const float* Rg    = (const float*)d_in[11];
    const float* L     = (const float*)d_in[12];
    const int*   step  = (const int*)d_in[13];

    int Btot = in_sizes[2] / D;
    if (Btot > MAXB) Btot = MAXB;
    int mtiles = Btot / BM;             // 64

    cudaFuncSetAttribute(gemm_kernel, cudaFuncAttributeMaxDynamicSharedMemorySize, SMEM_GEMM);

    convert_kernel<<<128, 256>>>(W, V, R, Rg, L);
    wwt_kernel<<<dim3(4, 4), 256>>>();
    cvec_kernel<<<8, 256>>>(W, b_out);
    elemwise_kernel<<<Btot / 8, 256>>>(x, xt1, xt2, xt3, bu, td);
    gemm_kernel<<<dim3(D / BN, mtiles, 4), 256, SMEM_GEMM>>>(b_in);
    gfuse_kernel<<<(Btot * D) / 4096, 256>>>();
    reduce_scale_kernel<<<1, 256>>>(step, (Btot * D) / 4096);
    finalize_kernel<<<1024, 256>>>(x, (float*)d_out, Btot * D / 4);
}

// round 12
// speedup vs baseline: 2.0839x; 1.2222x over previous
#include <cuda_runtime.h>
#include <cuda_bf16.h>
#include <mma.h>
#include <math.h>

using namespace nvcuda;

#define D      512
#define KWTA   128
#define MAXB   8192

// GEMM tiling
#define BM     128
#define BN     128
#define BK     32
#define LDAS   40
#define LDBS   136
#define LDE    132
#define STAGE_E (BM * LDAS + BK * LDBS)          // 9472 bf16 per stage
#define NSTAGE 3
#define PIPE_BYTES (NSTAGE * STAGE_E * 2)        // 56832
#define OFF_GATE   PIPE_BYTES
#define SMEM_GEMM  (PIPE_BYTES + BM * BN * 2)    // 89600 (2 CTAs -> 179KB < 228KB)
#define SMEM_WWT   PIPE_BYTES

#define NB_CONV 128
#define NB_CVEC 8
#define NPART   512

// ---------------- device scratch ----------------
__device__ __nv_bfloat16 g_Wb[D * D];            // W [O][I]
__device__ __nv_bfloat16 g_WTb[D * D];           // W^T [I][O]
__device__ __nv_bfloat16 g_nWWT[D * D];          // -(W W^T)
__device__ __nv_bfloat16 g_V15b[D * D];          // 1.5 V
__device__ __nv_bfloat16 g_Rb[D * D];
__device__ __nv_bfloat16 g_Rgb[D * D];
__device__ __nv_bfloat16 g_Lb[D * D];
__device__ float g_cvec[D];                      // c[o] = sum_i b_out[i] W[o][i]

__device__ __nv_bfloat16 g_phix[MAXB * D];
__device__ __nv_bfloat16 g_bub[MAXB * D];
__device__ __nv_bfloat16 g_ctx[MAXB * D];
__device__ __nv_bfloat16 g_phic[MAXB * D];
__device__ __nv_bfloat16 g_phid[MAXB * D];
__device__ __nv_bfloat16 g_tdx[MAXB * D];        // 3 td - 5.5 x - 1e-6 sign(x)
__device__ __nv_bfloat16 g_fb[MAXB * D];
__device__ __nv_bfloat16 g_P1[MAXB * D];
__device__ __nv_bfloat16 g_RG[MAXB * D];         // rec * gate
__device__ __nv_bfloat16 g_g[MAXB * D];

__device__ float g_part[NPART];
__device__ float g_scalef;

__device__ __forceinline__ float fast_tanh(float x) {
    float y;
    asm("tanh.approx.f32 %0, %1;" : "=f"(y) : "f"(x));
    return y;
}

// ---------------- exact register k-WTA with early exit ----------------
__device__ __forceinline__ void kwta_reg(const float v[16], float m[16]) {
    int lane = threadIdx.x & 31;
    unsigned u[16];
#pragma unroll
    for (int j = 0; j < 16; j++) {
        unsigned b = __float_as_uint(v[j]);
        u[j] = (b & 0x80000000u) ? ~b : (b | 0x80000000u);
    }
    unsigned prefix = 0;
    int exact = 0;
#pragma unroll 1
    for (int bit = 31; bit >= 0; --bit) {
        unsigned probe = prefix | (1u << bit);
        int c = 0;
#pragma unroll
        for (int j = 0; j < 16; j++) c += (u[j] >= probe);
        c = __reduce_add_sync(0xffffffffu, c);
        if (c >= KWTA) {
            prefix = probe;
            if (c == KWTA) { exact = 1; break; }
        }
    }
    if (exact) {
#pragma unroll
        for (int j = 0; j < 16; j++) m[j] = (u[j] >= prefix) ? 1.0f : 0.0f;
        return;
    }
    int cg = 0;
#pragma unroll
    for (int j = 0; j < 16; j++) cg += (u[j] > prefix);
    cg = __reduce_add_sync(0xffffffffu, cg);
    int remk = KWTA - cg;
    unsigned lmask = (1u << lane) - 1u;
    int running = 0;
#pragma unroll
    for (int j = 0; j < 16; j++) {
        bool eq = (u[j] == prefix);
        unsigned beq = __ballot_sync(0xffffffffu, eq);
        bool inc = (u[j] > prefix) || (eq && (running + __popc(beq & lmask)) < remk);
        running += __popc(beq);
        m[j] = inc ? 1.0f : 0.0f;
    }
}

// ---------------- fused prep: elemwise | convert | cvec ----------------
__global__ void __launch_bounds__(256) prep_kernel(
    const float* __restrict__ x, const float* __restrict__ xt1,
    const float* __restrict__ xt2, const float* __restrict__ xt3,
    const float* __restrict__ bu, const float* __restrict__ td,
    const float* __restrict__ W, const float* __restrict__ V,
    const float* __restrict__ R, const float* __restrict__ Rg,
    const float* __restrict__ L, const float* __restrict__ b_out,
    int nb_elem) {
    const int b = blockIdx.x;
    if (b < nb_elem) {
        // ---- elemwise: one warp per batch row ----
        const int warp = threadIdx.x >> 5, lane = threadIdx.x & 31;
        const size_t base = ((size_t)b * 8 + warp) * D;
        const float INV_SQRT2PI = 0.39894228040143267794f;
        const float GC0 = 0.79788456080286535588f;
        const float GC1 = 0.044715f;

        float v[16], m[16];
#pragma unroll
        for (int j = 0; j < 16; j++) v[j] = x[base + lane + 32 * j];
        kwta_reg(v, m);
#pragma unroll
        for (int j = 0; j < 16; j++) {
            size_t idx = base + lane + 32 * j;
            float val = v[j];
            float t = fast_tanh(GC0 * (val + GC1 * val * val * val));
            float cdf = 0.5f * (1.0f + t);
            float pdf = __expf(-0.5f * val * val) * INV_SQRT2PI;
            g_phix[idx] = __float2bfloat16(val * cdf * m[j]);
            g_phid[idx] = __float2bfloat16((cdf + val * pdf) * m[j]);
            g_bub[idx]  = __float2bfloat16(bu[idx]);
            float sgn = (val > 0.0f) ? 1.0f : ((val < 0.0f) ? -1.0f : 0.0f);
            g_tdx[idx]  = __float2bfloat16(3.0f * td[idx] - 5.5f * val - 1e-6f * sgn);
        }
        float c[16];
#pragma unroll
        for (int j = 0; j < 16; j++) {
            size_t idx = base + lane + 32 * j;
            c[j] = 0.5f * xt1[idx] + 0.3f * xt2[idx] + 0.2f * xt3[idx];
        }
        kwta_reg(c, m);
#pragma unroll
        for (int j = 0; j < 16; j++) {
            size_t idx = base + lane + 32 * j;
            float val = c[j];
            g_ctx[idx] = __float2bfloat16(val);
            float t = fast_tanh(GC0 * (val + GC1 * val * val * val));
            g_phic[idx] = __float2bfloat16(val * 0.5f * (1.0f + t) * m[j]);
        }
    } else if (b < nb_elem + NB_CONV) {
        // ---- weight conversion ----
        int bid = b - nb_elem;
        int n = D * D;
        for (int idx = bid * 256 + threadIdx.x; idx < n; idx += NB_CONV * 256) {
            int i = idx >> 9, j = idx & 511;
            float w = W[idx];
            g_Wb[idx]        = __float2bfloat16(w);
            g_WTb[j * D + i] = __float2bfloat16(w);
            g_V15b[idx]      = __float2bfloat16(1.5f * V[idx]);
            g_Rb[idx]        = __float2bfloat16(R[idx]);
            g_Rgb[idx]       = __float2bfloat16(Rg[idx]);
            g_Lb[idx]        = __float2bfloat16(L[idx]);
        }
    } else {
        // ---- cvec ----
        int bid = b - nb_elem - NB_CONV;
        int gw = (bid * 256 + threadIdx.x) >> 5;
        int lane = threadIdx.x & 31;
        for (int row = gw; row < D; row += NB_CVEC * 8) {
            float s = 0.0f;
            for (int j = 0; j < 16; j++) {
                int i = lane + 32 * j;
                s += b_out[i] * W[(size_t)row * D + i];
            }
#pragma unroll
            for (int o = 16; o > 0; o >>= 1) s += __shfl_xor_sync(0xffffffffu, s, o);
            if (lane == 0) g_cvec[row] = s;
        }
    }
}

// ---------------- cp.async helpers ----------------
__device__ __forceinline__ void cp16(void* s, const void* g) {
    unsigned sa = (unsigned)__cvta_generic_to_shared(s);
    asm volatile("cp.async.cg.shared.global [%0], [%1], 16;" :: "r"(sa), "l"(g));
}

__device__ __forceinline__ void load_stage(__nv_bfloat16* stage,
                                           const __nv_bfloat16* A0, const __nv_bfloat16* B0,
                                           const __nv_bfloat16* A1, const __nv_bfloat16* B1,
                                           int ks, int tid) {
    const __nv_bfloat16* Ag = (ks >= 16) ? A1 : A0;
    const __nv_bfloat16* Bg = (ks >= 16) ? B1 : B0;
    int k0 = (ks & 15) * BK;
    __nv_bfloat16* As = stage;
    __nv_bfloat16* Bs = stage + BM * LDAS;
#pragma unroll
    for (int t = 0; t < 2; t++) {
        int task = tid + t * 256;
        int arow = task >> 2, ach = task & 3;
        cp16(As + arow * LDAS + ach * 8, Ag + (size_t)arow * D + k0 + ach * 8);
        int brow = task >> 4, bch = task & 15;
        cp16(Bs + brow * LDBS + bch * 8, Bg + (size_t)(k0 + brow) * D + bch * 8);
    }
}

// ---------------- pipelined 128x128 tile core ----------------
__device__ __forceinline__ void run_gemm(
    const __nv_bfloat16* A0, const __nv_bfloat16* B0,
    const __nv_bfloat16* A1, const __nv_bfloat16* B1,
    int nk, __nv_bfloat16* smem, int tid, int wm, int wn,
    wmma::fragment<wmma::accumulator, 16, 16, 16, float> acc[4][2]) {
    load_stage(smem + 0 * STAGE_E, A0, B0, A1, B1, 0, tid);
    asm volatile("cp.async.commit_group;" ::: "memory");
    load_stage(smem + 1 * STAGE_E, A0, B0, A1, B1, 1, tid);
    asm volatile("cp.async.commit_group;" ::: "memory");
    for (int ki = 0; ki < nk; ki++) {
        asm volatile("cp.async.wait_group 1;" ::: "memory");
        __syncthreads();
        __nv_bfloat16* As = smem + (ki % NSTAGE) * STAGE_E;
        __nv_bfloat16* Bs = As + BM * LDAS;
#pragma unroll
        for (int kk = 0; kk < BK; kk += 16) {
            wmma::fragment<wmma::matrix_a, 16, 16, 16, __nv_bfloat16, wmma::row_major> af[4];
            wmma::fragment<wmma::matrix_b, 16, 16, 16, __nv_bfloat16, wmma::row_major> bf_[2];
#pragma unroll
            for (int i = 0; i < 4; i++)
                wmma::load_matrix_sync(af[i], As + (wm * 64 + i * 16) * LDAS + kk, LDAS);
#pragma unroll
            for (int j = 0; j < 2; j++)
                wmma::load_matrix_sync(bf_[j], Bs + kk * LDBS + wn * 32 + j * 16, LDBS);
#pragma unroll
            for (int i = 0; i < 4; i++)
#pragma unroll
                for (int j = 0; j < 2; j++)
                    wmma::mma_sync(acc[i][j], af[i], bf_[j], acc[i][j]);
        }
        if (ki + 2 < nk) load_stage(smem + ((ki + 2) % NSTAGE) * STAGE_E, A0, B0, A1, B1, ki + 2, tid);
        asm volatile("cp.async.commit_group;" ::: "memory");
    }
    asm volatile("cp.async.wait_group 0;" ::: "memory");
    __syncthreads();
}

// ---------------- wwt: -(W @ W^T) via pipelined core, 16 CTAs ----------------
__global__ void __launch_bounds__(256, 2) wwt_kernel() {
    extern __shared__ unsigned char smem_raw[];
    __nv_bfloat16* smem = (__nv_bfloat16*)smem_raw;
    const int tid = threadIdx.x, wid = tid >> 5;
    const int wm = wid >> 2, wn = wid & 3;
    const int m0 = blockIdx.y * BM, n0 = blockIdx.x * BN;

    wmma::fragment<wmma::accumulator, 16, 16, 16, float> acc[4][2];
#pragma unroll
    for (int i = 0; i < 4; i++)
#pragma unroll
        for (int j = 0; j < 2; j++) wmma::fill_fragment(acc[i][j], 0.0f);

    run_gemm(g_Wb + (size_t)m0 * D, g_WTb + n0, 0, 0, 16, smem, tid, wm, wn, acc);

    float* Es = (float*)smem_raw;
#pragma unroll 1
    for (int half = 0; half < 2; half++) {
        __syncthreads();
        if (wm == half)
#pragma unroll
            for (int i = 0; i < 4; i++)
#pragma unroll
                for (int j = 0; j < 2; j++)
                    wmma::store_matrix_sync(Es + (i * 16) * LDE + wn * 32 + j * 16,
                                            acc[i][j], LDE, wmma::mem_row_major);
        __syncthreads();
#pragma unroll 4
        for (int t = 0; t < 32; t++) {
            int idx = t * 256 + tid;
            int r = idx >> 7, c = idx & 127;
            g_nWWT[(size_t)(m0 + half * 64 + r) * D + n0 + c] = __float2bfloat16(-Es[r * LDE + c]);
        }
    }
}

// ---------------- main GEMM phase: 3 uniform modes (nk=32 each) ------------
// mode 0: fb = bub@W^T - phix@WWT - c
// mode 1: P1 = phix@L + bub@(1.5V) + 1.5 b_in + tdx
// mode 2: gate = sigmoid(ctx@Rg) [smem]; RG = (phic@R) * gate
__global__ void __launch_bounds__(256, 2) gemm_kernel(const float* __restrict__ b_in) {
    extern __shared__ unsigned char smem_raw[];
    __nv_bfloat16* smem = (__nv_bfloat16*)smem_raw;
    __nv_bfloat16* gatebuf = (__nv_bfloat16*)(smem_raw + OFF_GATE);
    float* Es = (float*)smem_raw;

    const int tid = threadIdx.x, wid = tid >> 5;
    const int wm = wid >> 2, wn = wid & 3;
    const int mode = blockIdx.z;
    const int n0 = blockIdx.x * BN, m0 = blockIdx.y * BM;

    wmma::fragment<wmma::accumulator, 16, 16, 16, float> acc[4][2];
#pragma unroll
    for (int i = 0; i < 4; i++)
#pragma unroll
        for (int j = 0; j < 2; j++) wmma::fill_fragment(acc[i][j], 0.0f);

    if (mode == 0) {
        run_gemm(g_bub + (size_t)m0 * D, g_WTb + n0,
                 g_phix + (size_t)m0 * D, g_nWWT + n0, 32, smem, tid, wm, wn, acc);
#pragma unroll 1
        for (int half = 0; half < 2; half++) {
            __syncthreads();
            if (wm == half)
#pragma unroll
                for (int i = 0; i < 4; i++)
#pragma unroll
                    for (int j = 0; j < 2; j++)
                        wmma::store_matrix_sync(Es + (i * 16) * LDE + wn * 32 + j * 16,
                                                acc[i][j], LDE, wmma::mem_row_major);
            __syncthreads();
#pragma unroll 4
            for (int t = 0; t < 32; t++) {
                int idx = t * 256 + tid;
                int r = idx >> 7, c = idx & 127;
                size_t gi = (size_t)(m0 + half * 64 + r) * D + n0 + c;
                g_fb[gi] = __float2bfloat16(Es[r * LDE + c] - g_cvec[n0 + c]);
            }
        }
    } else if (mode == 1) {
        run_gemm(g_phix + (size_t)m0 * D, g_Lb + n0,
                 g_bub + (size_t)m0 * D, g_V15b + n0, 32, smem, tid, wm, wn, acc);
#pragma unroll 1
        for (int half = 0; half < 2; half++) {
            __syncthreads();
            if (wm == half)
#pragma unroll
                for (int i = 0; i < 4; i++)
#pragma unroll
                    for (int j = 0; j < 2; j++)
                        wmma::store_matrix_sync(Es + (i * 16) * LDE + wn * 32 + j * 16,
                                                acc[i][j], LDE, wmma::mem_row_major);
            __syncthreads();
#pragma unroll 4
            for (int t = 0; t < 32; t++) {
                int idx = t * 256 + tid;
                int r = idx >> 7, c = idx & 127;
                int gc = n0 + c;
                size_t gi = (size_t)(m0 + half * 64 + r) * D + gc;
                g_P1[gi] = __float2bfloat16(Es[r * LDE + c] + 1.5f * b_in[gc]
                                            + __bfloat162float(g_tdx[gi]));
            }
        }
    } else {
        // pass 0: gate -> smem
        run_gemm(g_ctx + (size_t)m0 * D, g_Rgb + n0, 0, 0, 16, smem, tid, wm, wn, acc);
#pragma unroll 1
        for (int half = 0; half < 2; half++) {
            __syncthreads();
            if (wm == half)
#pragma unroll
                for (int i = 0; i < 4; i++)
#pragma unroll
                    for (int j = 0; j < 2; j++)
                        wmma::store_matrix_sync(Es + (i * 16) * LDE + wn * 32 + j * 16,
                                                acc[i][j], LDE, wmma::mem_row_major);
            __syncthreads();
#pragma unroll 4
            for (int t = 0; t < 32; t++) {
                int idx = t * 256 + tid;
                int r = idx >> 7, c = idx & 127;
                float v = Es[r * LDE + c];
                gatebuf[(half * 64 + r) * BN + c] = __float2bfloat16(1.0f / (1.0f + __expf(-v)));
            }
        }
        __syncthreads();
        // pass 1: rec, multiply by gate
#pragma unroll
        for (int i = 0; i < 4; i++)
#pragma unroll
            for (int j = 0; j < 2; j++) wmma::fill_fragment(acc[i][j], 0.0f);
        run_gemm(g_phic + (size_t)m0 * D, g_Rb + n0, 0, 0, 16, smem, tid, wm, wn, acc);
#pragma unroll 1
        for (int half = 0; half < 2; half++) {
            __syncthreads();
            if (wm == half)
#pragma unroll
                for (int i = 0; i < 4; i++)
#pragma unroll
                    for (int j = 0; j < 2; j++)
                        wmma::store_matrix_sync(Es + (i * 16) * LDE + wn * 32 + j * 16,
                                                acc[i][j], LDE, wmma::mem_row_major);
            __syncthreads();
#pragma unroll 4
            for (int t = 0; t < 32; t++) {
                int idx = t * 256 + tid;
                int r = idx >> 7, c = idx & 127;
                size_t gi = (size_t)(m0 + half * 64 + r) * D + n0 + c;
                float gate = __bfloat162float(gatebuf[(half * 64 + r) * BN + c]);
                g_RG[gi] = __float2bfloat16(Es[r * LDE + c] * gate);
            }
        }
    }
}

// ---------------- g = fb*phid + P1 + RG (+ partial sumsq) ------------------
__global__ void __launch_bounds__(256) gfuse_kernel() {
    __shared__ float red[256];
    const int tid = threadIdx.x;
    const int base = blockIdx.x * 2048;          // uint2 (4xbf16) units
    const uint2* fb4 = (const uint2*)g_fb;
    const uint2* pd4 = (const uint2*)g_phid;
    const uint2* p14 = (const uint2*)g_P1;
    const uint2* rg4 = (const uint2*)g_RG;
    uint2* gg4 = (uint2*)g_g;

    float ss = 0.0f;
#pragma unroll
    for (int t = 0; t < 8; t++) {
        int i = base + t * 256 + tid;
        uint2 fbu = fb4[i], pdu = pd4[i], p1u = p14[i], rgu = rg4[i];
        float2 fb0 = __bfloat1622float2(*(__nv_bfloat162*)&fbu.x);
        float2 fb1 = __bfloat1622float2(*(__nv_bfloat162*)&fbu.y);
        float2 pd0 = __bfloat1622float2(*(__nv_bfloat162*)&pdu.x);
        float2 pd1 = __bfloat1622float2(*(__nv_bfloat162*)&pdu.y);
        float2 p10 = __bfloat1622float2(*(__nv_bfloat162*)&p1u.x);
        float2 p11 = __bfloat1622float2(*(__nv_bfloat162*)&p1u.y);
        float2 rg0 = __bfloat1622float2(*(__nv_bfloat162*)&rgu.x);
        float2 rg1 = __bfloat1622float2(*(__nv_bfloat162*)&rgu.y);
        float ga = fb0.x * pd0.x + p10.x + rg0.x;
        float gb = fb0.y * pd0.y + p10.y + rg0.y;
        float gc = fb1.x * pd1.x + p11.x + rg1.x;
        float gd = fb1.y * pd1.y + p11.y + rg1.y;
        uint2 o;
        __nv_bfloat162 lo = __floats2bfloat162_rn(ga, gb);
        __nv_bfloat162 hi = __floats2bfloat162_rn(gc, gd);
        o.x = *(unsigned*)&lo; o.y = *(unsigned*)&hi;
        gg4[i] = o;
        ss += ga * ga + gb * gb + gc * gc + gd * gd;
    }
    red[tid] = ss;
    __syncthreads();
    for (int o = 128; o > 0; o >>= 1) {
        if (tid < o) red[tid] += red[tid + o];
        __syncthreads();
    }
    if (tid == 0) g_part[blockIdx.x] = red[0];
}

// ---------------- global norm -> clip scale ----------------
__global__ void reduce_scale_kernel(const int* __restrict__ step_i, int nparts) {
    __shared__ float red[256];
    float s = 0.0f;
    for (int i = threadIdx.x; i < nparts; i += 256) s += g_part[i];
    red[threadIdx.x] = s;
    __syncthreads();
    for (int o = 128; o > 0; o >>= 1) {
        if (threadIdx.x < o) red[threadIdx.x] += red[threadIdx.x + o];
        __syncthreads();
    }
    if (threadIdx.x == 0) {
        float eta = 0.8f / (1.0f + 0.1f * (float)step_i[0]);
        float cc = 0.5f * eta;                   // TAU * eta
        float n = cc * sqrtf(red[0]);
        float sc = (n > 1.0f) ? (1.0f / (n + 1e-8f)) : 1.0f;
        g_scalef = cc * sc;
    }
}

// ---------------- finalize: x_new = clip(x + g*scale, -5, 5) ----------------
__global__ void finalize_kernel(const float* __restrict__ x, float* __restrict__ out, int n4) {
    float f = g_scalef;
    const float4* x4 = (const float4*)x;
    const uint2* gg = (const uint2*)g_g;
    float4* o4 = (float4*)out;
    for (int i = blockIdx.x * blockDim.x + threadIdx.x; i < n4; i += gridDim.x * blockDim.x) {
        float4 xv = x4[i];
        uint2 gpack = gg[i];
        float2 g0 = __bfloat1622float2(*(__nv_bfloat162*)&gpack.x);
        float2 g1 = __bfloat1622float2(*(__nv_bfloat162*)&gpack.y);
        float4 o;
        o.x = fminf(5.0f, fmaxf(-5.0f, xv.x + g0.x * f));
        o.y = fminf(5.0f, fmaxf(-5.0f, xv.y + g0.y * f));
        o.z = fminf(5.0f, fmaxf(-5.0f, xv.z + g1.x * f));
        o.w = fminf(5.0f, fmaxf(-5.0f, xv.w + g1.y * f));
        o4[i] = o;
    }
}

extern "C" void kernel_launch(void* const* d_in, const int* in_sizes, int n_in,
                              void* d_out, int out_size) {
    const float* bu    = (const float*)d_in[0];
    const float* td    = (const float*)d_in[1];
    const float* x     = (const float*)d_in[2];
    const float* xt1   = (const float*)d_in[3];
    const float* xt2   = (const float*)d_in[4];
    const float* xt3   = (const float*)d_in[5];
    const float* V     = (const float*)d_in[6];
    const float* b_in  = (const float*)d_in[7];
    const float* W     = (const float*)d_in[8];
    const float* b_out = (const float*)d_in[9];
    const float* R     = (const float*)d_in[10];
    const float* Rg    = (const float*)d_in[11];
    const float* L     = (const float*)d_in[12];
    const int*   step  = (const int*)d_in[13];

    int Btot = in_sizes[2] / D;
    if (Btot > MAXB) Btot = MAXB;
    int mtiles = Btot / BM;             // 64
    int nb_elem = Btot / 8;             // 1024

    cudaFuncSetAttribute(gemm_kernel, cudaFuncAttributeMaxDynamicSharedMemorySize, SMEM_GEMM);
    cudaFuncSetAttribute(wwt_kernel, cudaFuncAttributeMaxDynamicSharedMemorySize, SMEM_WWT);

    prep_kernel<<<nb_elem + NB_CONV + NB_CVEC, 256>>>(x, xt1, xt2, xt3, bu, td,
                                                      W, V, R, Rg, L, b_out, nb_elem);
    wwt_kernel<<<dim3(4, 4), 256, SMEM_WWT>>>();
    gemm_kernel<<<dim3(D / BN, mtiles, 3), 256, SMEM_GEMM>>>(b_in);
    gfuse_kernel<<<(Btot * D) / 8192, 256>>>();
    reduce_scale_kernel<<<1, 256>>>(step, (Btot * D) / 8192);
    finalize_kernel<<<1024, 256>>>(x, (float*)d_out, Btot * D / 4);
}

// round 13
// speedup vs baseline: 2.1849x; 1.0485x over previous
#include <cuda_runtime.h>
#include <cuda_bf16.h>
#include <mma.h>
#include <math.h>

using namespace nvcuda;

#define D      512
#define KWTA   128
#define MAXB   8192

// GEMM tiling (uniform nk=16 slices, 2 CTAs/SM)
#define BM     128
#define BN     128
#define BK     32
#define LDAS   40
#define LDBS   136
#define LDE    132
#define STAGE_E (BM * LDAS + BK * LDBS)          // 9472 bf16 per stage
#define NSTAGE 3
#define SMEM_GEMM (NSTAGE * STAGE_E * 2)         // 56832 bytes

#define NB_CONV 128
#define NB_CVEC 8
#define NPART   512

// ---------------- device scratch ----------------
__device__ __nv_bfloat16 g_Wb[D * D];            // W [O][I]
__device__ __nv_bfloat16 g_WTb[D * D];           // W^T [I][O]
__device__ __nv_bfloat16 g_nWWT[D * D];          // -(W W^T)
__device__ __nv_bfloat16 g_V15b[D * D];          // 1.5 V
__device__ __nv_bfloat16 g_Rb[D * D];
__device__ __nv_bfloat16 g_Rgb[D * D];
__device__ __nv_bfloat16 g_Lb[D * D];
__device__ float g_cvec[D];                      // c[o] = sum_i b_out[i] W[o][i]

__device__ __nv_bfloat16 g_phix[MAXB * D];
__device__ __nv_bfloat16 g_bub[MAXB * D];
__device__ __nv_bfloat16 g_ctx[MAXB * D];
__device__ __nv_bfloat16 g_phic[MAXB * D];
__device__ __nv_bfloat16 g_phid[MAXB * D];
__device__ __nv_bfloat16 g_tdx[MAXB * D];        // 3 td - 5.5 x - 1e-6 sign(x) + 1.5 b_in
__device__ __nv_bfloat16 g_t0[MAXB * D];         // bub@W^T
__device__ __nv_bfloat16 g_t1[MAXB * D];         // phix@(-WWT)
__device__ __nv_bfloat16 g_t2[MAXB * D];         // phix@L
__device__ __nv_bfloat16 g_t3[MAXB * D];         // bub@(1.5V)
__device__ __nv_bfloat16 g_gate[MAXB * D];
__device__ __nv_bfloat16 g_rec[MAXB * D];
__device__ __nv_bfloat16 g_g[MAXB * D];

__device__ float g_part[NPART];
__device__ float g_scalef;

__device__ __forceinline__ float fast_tanh(float x) {
    float y;
    asm("tanh.approx.f32 %0, %1;" : "=f"(y) : "f"(x));
    return y;
}

// ---------------- exact register k-WTA with early exit ----------------
__device__ __forceinline__ void kwta_reg(const float v[16], float m[16]) {
    int lane = threadIdx.x & 31;
    unsigned u[16];
#pragma unroll
    for (int j = 0; j < 16; j++) {
        unsigned b = __float_as_uint(v[j]);
        u[j] = (b & 0x80000000u) ? ~b : (b | 0x80000000u);
    }
    unsigned prefix = 0;
    int exact = 0;
#pragma unroll 1
    for (int bit = 31; bit >= 0; --bit) {
        unsigned probe = prefix | (1u << bit);
        int c = 0;
#pragma unroll
        for (int j = 0; j < 16; j++) c += (u[j] >= probe);
        c = __reduce_add_sync(0xffffffffu, c);
        if (c >= KWTA) {
            prefix = probe;
            if (c == KWTA) { exact = 1; break; }
        }
    }
    if (exact) {
#pragma unroll
        for (int j = 0; j < 16; j++) m[j] = (u[j] >= prefix) ? 1.0f : 0.0f;
        return;
    }
    int cg = 0;
#pragma unroll
    for (int j = 0; j < 16; j++) cg += (u[j] > prefix);
    cg = __reduce_add_sync(0xffffffffu, cg);
    int remk = KWTA - cg;
    unsigned lmask = (1u << lane) - 1u;
    int running = 0;
#pragma unroll
    for (int j = 0; j < 16; j++) {
        bool eq = (u[j] == prefix);
        unsigned beq = __ballot_sync(0xffffffffu, eq);
        bool inc = (u[j] > prefix) || (eq && (running + __popc(beq & lmask)) < remk);
        running += __popc(beq);
        m[j] = inc ? 1.0f : 0.0f;
    }
}

// ---------------- fused prep: elemwise | convert | cvec ----------------
__global__ void __launch_bounds__(256) prep_kernel(
    const float* __restrict__ x, const float* __restrict__ xt1,
    const float* __restrict__ xt2, const float* __restrict__ xt3,
    const float* __restrict__ bu, const float* __restrict__ td,
    const float* __restrict__ W, const float* __restrict__ V,
    const float* __restrict__ R, const float* __restrict__ Rg,
    const float* __restrict__ L, const float* __restrict__ b_out,
    const float* __restrict__ b_in, int nb_elem) {
    const int b = blockIdx.x;
    if (b < nb_elem) {
        // ---- elemwise: one warp per batch row ----
        const int warp = threadIdx.x >> 5, lane = threadIdx.x & 31;
        const size_t base = ((size_t)b * 8 + warp) * D;
        const float INV_SQRT2PI = 0.39894228040143267794f;
        const float GC0 = 0.79788456080286535588f;
        const float GC1 = 0.044715f;

        float v[16], m[16];
#pragma unroll
        for (int j = 0; j < 16; j++) v[j] = x[base + lane + 32 * j];
        kwta_reg(v, m);
#pragma unroll
        for (int j = 0; j < 16; j++) {
            size_t idx = base + lane + 32 * j;
            int col = lane + 32 * j;
            float val = v[j];
            float t = fast_tanh(GC0 * (val + GC1 * val * val * val));
            float cdf = 0.5f * (1.0f + t);
            float pdf = __expf(-0.5f * val * val) * INV_SQRT2PI;
            g_phix[idx] = __float2bfloat16(val * cdf * m[j]);
            g_phid[idx] = __float2bfloat16((cdf + val * pdf) * m[j]);
            g_bub[idx]  = __float2bfloat16(bu[idx]);
            float sgn = (val > 0.0f) ? 1.0f : ((val < 0.0f) ? -1.0f : 0.0f);
            g_tdx[idx]  = __float2bfloat16(3.0f * td[idx] - 5.5f * val - 1e-6f * sgn
                                           + 1.5f * b_in[col]);
        }
        float c[16];
#pragma unroll
        for (int j = 0; j < 16; j++) {
            size_t idx = base + lane + 32 * j;
            c[j] = 0.5f * xt1[idx] + 0.3f * xt2[idx] + 0.2f * xt3[idx];
        }
        kwta_reg(c, m);
#pragma unroll
        for (int j = 0; j < 16; j++) {
            size_t idx = base + lane + 32 * j;
            float val = c[j];
            g_ctx[idx] = __float2bfloat16(val);
            float t = fast_tanh(GC0 * (val + GC1 * val * val * val));
            g_phic[idx] = __float2bfloat16(val * 0.5f * (1.0f + t) * m[j]);
        }
    } else if (b < nb_elem + NB_CONV) {
        // ---- weight conversion ----
        int bid = b - nb_elem;
        int n = D * D;
        for (int idx = bid * 256 + threadIdx.x; idx < n; idx += NB_CONV * 256) {
            int i = idx >> 9, j = idx & 511;
            float w = W[idx];
            g_Wb[idx]        = __float2bfloat16(w);
            g_WTb[j * D + i] = __float2bfloat16(w);
            g_V15b[idx]      = __float2bfloat16(1.5f * V[idx]);
            g_Rb[idx]        = __float2bfloat16(R[idx]);
            g_Rgb[idx]       = __float2bfloat16(Rg[idx]);
            g_Lb[idx]        = __float2bfloat16(L[idx]);
        }
    } else {
        // ---- cvec ----
        int bid = b - nb_elem - NB_CONV;
        int gw = (bid * 256 + threadIdx.x) >> 5;
        int lane = threadIdx.x & 31;
        for (int row = gw; row < D; row += NB_CVEC * 8) {
            float s = 0.0f;
            for (int j = 0; j < 16; j++) {
                int i = lane + 32 * j;
                s += b_out[i] * W[(size_t)row * D + i];
            }
#pragma unroll
            for (int o = 16; o > 0; o >>= 1) s += __shfl_xor_sync(0xffffffffu, s, o);
            if (lane == 0) g_cvec[row] = s;
        }
    }
}

// ---------------- cp.async helpers ----------------
__device__ __forceinline__ void cp16(void* s, const void* g) {
    unsigned sa = (unsigned)__cvta_generic_to_shared(s);
    asm volatile("cp.async.cg.shared.global [%0], [%1], 16;" :: "r"(sa), "l"(g));
}

__device__ __forceinline__ void load_stage(__nv_bfloat16* stage,
                                           const __nv_bfloat16* Ag,
                                           const __nv_bfloat16* Bg,
                                           int ks, int tid) {
    int k0 = ks * BK;
    __nv_bfloat16* As = stage;
    __nv_bfloat16* Bs = stage + BM * LDAS;
#pragma unroll
    for (int t = 0; t < 2; t++) {
        int task = tid + t * 256;
        int arow = task >> 2, ach = task & 3;
        cp16(As + arow * LDAS + ach * 8, Ag + (size_t)arow * D + k0 + ach * 8);
        int brow = task >> 4, bch = task & 15;
        cp16(Bs + brow * LDBS + bch * 8, Bg + (size_t)(k0 + brow) * D + bch * 8);
    }
}

// ---------------- pipelined 128x128 tile core (nk=16) ----------------
__device__ __forceinline__ void run_gemm(
    const __nv_bfloat16* Ag, const __nv_bfloat16* Bg,
    __nv_bfloat16* smem, int tid, int wm, int wn,
    wmma::fragment<wmma::accumulator, 16, 16, 16, float> acc[4][2]) {
    load_stage(smem + 0 * STAGE_E, Ag, Bg, 0, tid);
    asm volatile("cp.async.commit_group;" ::: "memory");
    load_stage(smem + 1 * STAGE_E, Ag, Bg, 1, tid);
    asm volatile("cp.async.commit_group;" ::: "memory");
    for (int ki = 0; ki < 16; ki++) {
        asm volatile("cp.async.wait_group 1;" ::: "memory");
        __syncthreads();
        __nv_bfloat16* As = smem + (ki % NSTAGE) * STAGE_E;
        __nv_bfloat16* Bs = As + BM * LDAS;
#pragma unroll
        for (int kk = 0; kk < BK; kk += 16) {
            wmma::fragment<wmma::matrix_a, 16, 16, 16, __nv_bfloat16, wmma::row_major> af[4];
            wmma::fragment<wmma::matrix_b, 16, 16, 16, __nv_bfloat16, wmma::row_major> bf_[2];
#pragma unroll
            for (int i = 0; i < 4; i++)
                wmma::load_matrix_sync(af[i], As + (wm * 64 + i * 16) * LDAS + kk, LDAS);
#pragma unroll
            for (int j = 0; j < 2; j++)
                wmma::load_matrix_sync(bf_[j], Bs + kk * LDBS + wn * 32 + j * 16, LDBS);
#pragma unroll
            for (int i = 0; i < 4; i++)
#pragma unroll
                for (int j = 0; j < 2; j++)
                    wmma::mma_sync(acc[i][j], af[i], bf_[j], acc[i][j]);
        }
        if (ki + 2 < 16) load_stage(smem + ((ki + 2) % NSTAGE) * STAGE_E, Ag, Bg, ki + 2, tid);
        asm volatile("cp.async.commit_group;" ::: "memory");
    }
    asm volatile("cp.async.wait_group 0;" ::: "memory");
    __syncthreads();
}

// ---------------- wwt: -(W @ W^T) via pipelined core, 16 CTAs ----------------
__global__ void __launch_bounds__(256, 2) wwt_kernel() {
    extern __shared__ unsigned char smem_raw[];
    __nv_bfloat16* smem = (__nv_bfloat16*)smem_raw;
    const int tid = threadIdx.x, wid = tid >> 5;
    const int wm = wid >> 2, wn = wid & 3;
    const int m0 = blockIdx.y * BM, n0 = blockIdx.x * BN;

    wmma::fragment<wmma::accumulator, 16, 16, 16, float> acc[4][2];
#pragma unroll
    for (int i = 0; i < 4; i++)
#pragma unroll
        for (int j = 0; j < 2; j++) wmma::fill_fragment(acc[i][j], 0.0f);

    run_gemm(g_Wb + (size_t)m0 * D, g_WTb + n0, smem, tid, wm, wn, acc);

    float* Es = (float*)smem_raw;
#pragma unroll 1
    for (int half = 0; half < 2; half++) {
        __syncthreads();
        if (wm == half)
#pragma unroll
            for (int i = 0; i < 4; i++)
#pragma unroll
                for (int j = 0; j < 2; j++)
                    wmma::store_matrix_sync(Es + (i * 16) * LDE + wn * 32 + j * 16,
                                            acc[i][j], LDE, wmma::mem_row_major);
        __syncthreads();
#pragma unroll 4
        for (int t = 0; t < 32; t++) {
            int idx = t * 256 + tid;
            int r = idx >> 7, c = idx & 127;
            g_nWWT[(size_t)(m0 + half * 64 + r) * D + n0 + c] = __float2bfloat16(-Es[r * LDE + c]);
        }
    }
}

// ---------------- main GEMM phase: 6 uniform nk=16 slices ----------------
// z0: t0 = bub@W^T      z1: t1 = phix@(-WWT)   z2: t2 = phix@L
// z3: t3 = bub@(1.5V)   z4: gate = sigmoid(ctx@Rg)   z5: rec = phic@R
__global__ void __launch_bounds__(256, 2) gemm_kernel() {
    extern __shared__ unsigned char smem_raw[];
    __nv_bfloat16* smem = (__nv_bfloat16*)smem_raw;
    float* Es = (float*)smem_raw;

    const int tid = threadIdx.x, wid = tid >> 5;
    const int wm = wid >> 2, wn = wid & 3;
    const int mode = blockIdx.z;
    const int n0 = blockIdx.x * BN, m0 = blockIdx.y * BM;

    const __nv_bfloat16 *A, *B;
    __nv_bfloat16* O;
    int sig = 0;
    switch (mode) {
        case 0: A = g_bub;  B = g_WTb;  O = g_t0; break;
        case 1: A = g_phix; B = g_nWWT; O = g_t1; break;
        case 2: A = g_phix; B = g_Lb;   O = g_t2; break;
        case 3: A = g_bub;  B = g_V15b; O = g_t3; break;
        case 4: A = g_ctx;  B = g_Rgb;  O = g_gate; sig = 1; break;
        default: A = g_phic; B = g_Rb;  O = g_rec; break;
    }

    wmma::fragment<wmma::accumulator, 16, 16, 16, float> acc[4][2];
#pragma unroll
    for (int i = 0; i < 4; i++)
#pragma unroll
        for (int j = 0; j < 2; j++) wmma::fill_fragment(acc[i][j], 0.0f);

    run_gemm(A + (size_t)m0 * D, B + n0, smem, tid, wm, wn, acc);

#pragma unroll 1
    for (int half = 0; half < 2; half++) {
        __syncthreads();
        if (wm == half)
#pragma unroll
            for (int i = 0; i < 4; i++)
#pragma unroll
                for (int j = 0; j < 2; j++)
                    wmma::store_matrix_sync(Es + (i * 16) * LDE + wn * 32 + j * 16,
                                            acc[i][j], LDE, wmma::mem_row_major);
        __syncthreads();
#pragma unroll 4
        for (int t = 0; t < 32; t++) {
            int idx = t * 256 + tid;
            int r = idx >> 7, c = idx & 127;
            size_t gi = (size_t)(m0 + half * 64 + r) * D + n0 + c;
            float v = Es[r * LDE + c];
            if (sig) v = 1.0f / (1.0f + __expf(-v));
            O[gi] = __float2bfloat16(v);
        }
    }
}

// ---------------- g = (t0+t1-cvec)*phid + t2 + t3 + tdx + rec*gate ---------
__global__ void __launch_bounds__(256) gfuse_kernel() {
    __shared__ float red[256];
    const int tid = threadIdx.x;
    const int base = blockIdx.x * 2048;          // uint2 (4xbf16) units
    const uint2* t04 = (const uint2*)g_t0;
    const uint2* t14 = (const uint2*)g_t1;
    const uint2* t24 = (const uint2*)g_t2;
    const uint2* t34 = (const uint2*)g_t3;
    const uint2* pd4 = (const uint2*)g_phid;
    const uint2* tx4 = (const uint2*)g_tdx;
    const uint2* rc4 = (const uint2*)g_rec;
    const uint2* gt4 = (const uint2*)g_gate;
    const float4* cv4 = (const float4*)g_cvec;
    uint2* gg4 = (uint2*)g_g;

    float ss = 0.0f;
#pragma unroll
    for (int t = 0; t < 8; t++) {
        int i = base + t * 256 + tid;
        float4 cv = cv4[i & 127];
        uint2 u0 = t04[i], u1 = t14[i], u2 = t24[i], u3 = t34[i];
        uint2 up = pd4[i], ut = tx4[i], ur = rc4[i], ug = gt4[i];
        float2 a0 = __bfloat1622float2(*(__nv_bfloat162*)&u0.x);
        float2 a1 = __bfloat1622float2(*(__nv_bfloat162*)&u0.y);
        float2 b0 = __bfloat1622float2(*(__nv_bfloat162*)&u1.x);
        float2 b1 = __bfloat1622float2(*(__nv_bfloat162*)&u1.y);
        float2 c0 = __bfloat1622float2(*(__nv_bfloat162*)&u2.x);
        float2 c1 = __bfloat1622float2(*(__nv_bfloat162*)&u2.y);
        float2 d0 = __bfloat1622float2(*(__nv_bfloat162*)&u3.x);
        float2 d1 = __bfloat1622float2(*(__nv_bfloat162*)&u3.y);
        float2 p0 = __bfloat1622float2(*(__nv_bfloat162*)&up.x);
        float2 p1 = __bfloat1622float2(*(__nv_bfloat162*)&up.y);
        float2 x0 = __bfloat1622float2(*(__nv_bfloat162*)&ut.x);
        float2 x1 = __bfloat1622float2(*(__nv_bfloat162*)&ut.y);
        float2 r0 = __bfloat1622float2(*(__nv_bfloat162*)&ur.x);
        float2 r1 = __bfloat1622float2(*(__nv_bfloat162*)&ur.y);
        float2 s0 = __bfloat1622float2(*(__nv_bfloat162*)&ug.x);
        float2 s1 = __bfloat1622float2(*(__nv_bfloat162*)&ug.y);
        float ga = (a0.x + b0.x - cv.x) * p0.x + c0.x + d0.x + x0.x + r0.x * s0.x;
        float gb = (a0.y + b0.y - cv.y) * p0.y + c0.y + d0.y + x0.y + r0.y * s0.y;
        float gc = (a1.x + b1.x - cv.z) * p1.x + c1.x + d1.x + x1.x + r1.x * s1.x;
        float gd = (a1.y + b1.y - cv.w) * p1.y + c1.y + d1.y + x1.y + r1.y * s1.y;
        uint2 o;
        __nv_bfloat162 lo = __floats2bfloat162_rn(ga, gb);
        __nv_bfloat162 hi = __floats2bfloat162_rn(gc, gd);
        o.x = *(unsigned*)&lo; o.y = *(unsigned*)&hi;
        gg4[i] = o;
        ss += ga * ga + gb * gb + gc * gc + gd * gd;
    }
    red[tid] = ss;
    __syncthreads();
    for (int o = 128; o > 0; o >>= 1) {
        if (tid < o) red[tid] += red[tid + o];
        __syncthreads();
    }
    if (tid == 0) g_part[blockIdx.x] = red[0];
}

// ---------------- global norm -> clip scale ----------------
__global__ void reduce_scale_kernel(const int* __restrict__ step_i, int nparts) {
    __shared__ float red[256];
    float s = 0.0f;
    for (int i = threadIdx.x; i < nparts; i += 256) s += g_part[i];
    red[threadIdx.x] = s;
    __syncthreads();
    for (int o = 128; o > 0; o >>= 1) {
        if (threadIdx.x < o) red[threadIdx.x] += red[threadIdx.x + o];
        __syncthreads();
    }
    if (threadIdx.x == 0) {
        float eta = 0.8f / (1.0f + 0.1f * (float)step_i[0]);
        float cc = 0.5f * eta;                   // TAU * eta
        float n = cc * sqrtf(red[0]);
        float sc = (n > 1.0f) ? (1.0f / (n + 1e-8f)) : 1.0f;
        g_scalef = cc * sc;
    }
}

// ---------------- finalize: x_new = clip(x + g*scale, -5, 5) ----------------
__global__ void finalize_kernel(const float* __restrict__ x, float* __restrict__ out, int n4) {
    float f = g_scalef;
    const float4* x4 = (const float4*)x;
    const uint2* gg = (const uint2*)g_g;
    float4* o4 = (float4*)out;
    for (int i = blockIdx.x * blockDim.x + threadIdx.x; i < n4; i += gridDim.x * blockDim.x) {
        float4 xv = x4[i];
        uint2 gpack = gg[i];
        float2 g0 = __bfloat1622float2(*(__nv_bfloat162*)&gpack.x);
        float2 g1 = __bfloat1622float2(*(__nv_bfloat162*)&gpack.y);
        float4 o;
        o.x = fminf(5.0f, fmaxf(-5.0f, xv.x + g0.x * f));
        o.y = fminf(5.0f, fmaxf(-5.0f, xv.y + g0.y * f));
        o.z = fminf(5.0f, fmaxf(-5.0f, xv.z + g1.x * f));
        o.w = fminf(5.0f, fmaxf(-5.0f, xv.w + g1.y * f));
        o4[i] = o;
    }
}

extern "C" void kernel_launch(void* const* d_in, const int* in_sizes, int n_in,
                              void* d_out, int out_size) {
    const float* bu    = (const float*)d_in[0];
    const float* td    = (const float*)d_in[1];
    const float* x     = (const float*)d_in[2];
    const float* xt1   = (const float*)d_in[3];
    const float* xt2   = (const float*)d_in[4];
    const float* xt3   = (const float*)d_in[5];
    const float* V     = (const float*)d_in[6];
    const float* b_in  = (const float*)d_in[7];
    const float* W     = (const float*)d_in[8];
    const float* b_out = (const float*)d_in[9];
    const float* R     = (const float*)d_in[10];
    const float* Rg    = (const float*)d_in[11];
    const float* L     = (const float*)d_in[12];
    const int*   step  = (const int*)d_in[13];

    int Btot = in_sizes[2] / D;
    if (Btot > MAXB) Btot = MAXB;
    int mtiles = Btot / BM;             // 64
    int nb_elem = Btot / 8;             // 1024

    cudaFuncSetAttribute(gemm_kernel, cudaFuncAttributeMaxDynamicSharedMemorySize, SMEM_GEMM);
    cudaFuncSetAttribute(wwt_kernel, cudaFuncAttributeMaxDynamicSharedMemorySize, SMEM_GEMM);

    prep_kernel<<<nb_elem + NB_CONV + NB_CVEC, 256>>>(x, xt1, xt2, xt3, bu, td,
                                                      W, V, R, Rg, L, b_out, b_in, nb_elem);
    wwt_kernel<<<dim3(4, 4), 256, SMEM_GEMM>>>();
    gemm_kernel<<<dim3(D / BN, mtiles, 6), 256, SMEM_GEMM>>>();
    gfuse_kernel<<<(Btot * D) / 8192, 256>>>();
    reduce_scale_kernel<<<1, 256>>>(step, (Btot * D) / 8192);
    finalize_kernel<<<1024, 256>>>(x, (float*)d_out, Btot * D / 4);
}

// round 17
// speedup vs baseline: 2.2433x; 1.0268x over previous
#include <cuda_runtime.h>
#include <cuda_bf16.h>
#include <mma.h>
#include <math.h>

using namespace nvcuda;

#define D      512
#define KWTA   128
#define MAXB   8192

// GEMM tiling: BK=64, 3-stage, 2 CTAs/SM (215KB smem, 128 regs capped)
#define BM     128
#define BN     128
#define BK     64
#define NK     8
#define LDAS   72
#define LDBS   136
#define LDE    132
#define STAGE_E (BM * LDAS + BK * LDBS)          // 17920 bf16 per stage
#define NSTAGE 3
#define SMEM_GEMM (NSTAGE * STAGE_E * 2)         // 107520 bytes

#define NB_CONV 128
#define NB_CVEC 8
#define NPART   512

// ---------------- device scratch ----------------
__device__ __nv_bfloat16 g_Wb[D * D];            // W [O][I]
__device__ __nv_bfloat16 g_WTb[D * D];           // W^T [I][O]
__device__ __nv_bfloat16 g_nWWT[D * D];          // -(W W^T)
__device__ __nv_bfloat16 g_V15b[D * D];          // 1.5 V
__device__ __nv_bfloat16 g_Rb[D * D];
__device__ __nv_bfloat16 g_Rgb[D * D];
__device__ __nv_bfloat16 g_Lb[D * D];
__device__ float g_cvec[D];                      // c[o] = sum_i b_out[i] W[o][i]

__device__ __nv_bfloat16 g_phix[MAXB * D];
__device__ __nv_bfloat16 g_bub[MAXB * D];
__device__ __nv_bfloat16 g_ctx[MAXB * D];
__device__ __nv_bfloat16 g_phic[MAXB * D];
__device__ __nv_bfloat16 g_phid[MAXB * D];
__device__ __nv_bfloat16 g_tdx[MAXB * D];        // 3 td - 5.5 x - 1e-6 sign(x) + 1.5 b_in
__device__ __nv_bfloat16 g_t0[MAXB * D];         // bub@W^T
__device__ __nv_bfloat16 g_t1[MAXB * D];         // phix@(-WWT)
__device__ __nv_bfloat16 g_t2[MAXB * D];         // phix@L
__device__ __nv_bfloat16 g_t3[MAXB * D];         // bub@(1.5V)
__device__ __nv_bfloat16 g_gate[MAXB * D];
__device__ __nv_bfloat16 g_rec[MAXB * D];
__device__ __nv_bfloat16 g_g[MAXB * D];

__device__ float g_part[NPART];
__device__ float g_scalef;

__device__ __forceinline__ float fast_tanh(float x) {
    float y;
    asm("tanh.approx.f32 %0, %1;" : "=f"(y) : "f"(x));
    return y;
}

// ---------------- exact register k-WTA with early exit ----------------
__device__ __forceinline__ void kwta_reg(const float v[16], float m[16]) {
    int lane = threadIdx.x & 31;
    unsigned u[16];
#pragma unroll
    for (int j = 0; j < 16; j++) {
        unsigned b = __float_as_uint(v[j]);
        u[j] = (b & 0x80000000u) ? ~b : (b | 0x80000000u);
    }
    unsigned prefix = 0;
    int exact = 0;
#pragma unroll 1
    for (int bit = 31; bit >= 0; --bit) {
        unsigned probe = prefix | (1u << bit);
        int c = 0;
#pragma unroll
        for (int j = 0; j < 16; j++) c += (u[j] >= probe);
        c = __reduce_add_sync(0xffffffffu, c);
        if (c >= KWTA) {
            prefix = probe;
            if (c == KWTA) { exact = 1; break; }
        }
    }
    if (exact) {
#pragma unroll
        for (int j = 0; j < 16; j++) m[j] = (u[j] >= prefix) ? 1.0f : 0.0f;
        return;
    }
    int cg = 0;
#pragma unroll
    for (int j = 0; j < 16; j++) cg += (u[j] > prefix);
    cg = __reduce_add_sync(0xffffffffu, cg);
    int remk = KWTA - cg;
    unsigned lmask = (1u << lane) - 1u;
    int running = 0;
#pragma unroll
    for (int j = 0; j < 16; j++) {
        bool eq = (u[j] == prefix);
        unsigned beq = __ballot_sync(0xffffffffu, eq);
        bool inc = (u[j] > prefix) || (eq && (running + __popc(beq & lmask)) < remk);
        running += __popc(beq);
        m[j] = inc ? 1.0f : 0.0f;
    }
}

// ---------------- fused prep: elemwise | convert | cvec ----------------
__global__ void __launch_bounds__(256) prep_kernel(
    const float* __restrict__ x, const float* __restrict__ xt1,
    const float* __restrict__ xt2, const float* __restrict__ xt3,
    const float* __restrict__ bu, const float* __restrict__ td,
    const float* __restrict__ W, const float* __restrict__ V,
    const float* __restrict__ R, const float* __restrict__ Rg,
    const float* __restrict__ L, const float* __restrict__ b_out,
    const float* __restrict__ b_in, int nb_elem) {
    const int b = blockIdx.x;
    if (b < nb_elem) {
        // ---- elemwise: one warp per batch row ----
        const int warp = threadIdx.x >> 5, lane = threadIdx.x & 31;
        const size_t base = ((size_t)b * 8 + warp) * D;
        const float INV_SQRT2PI = 0.39894228040143267794f;
        const float GC0 = 0.79788456080286535588f;
        const float GC1 = 0.044715f;

        float v[16], m[16];
#pragma unroll
        for (int j = 0; j < 16; j++) v[j] = x[base + lane + 32 * j];
        kwta_reg(v, m);
#pragma unroll
        for (int j = 0; j < 16; j++) {
            size_t idx = base + lane + 32 * j;
            int col = lane + 32 * j;
            float val = v[j];
            float t = fast_tanh(GC0 * (val + GC1 * val * val * val));
            float cdf = 0.5f * (1.0f + t);
            float pdf = __expf(-0.5f * val * val) * INV_SQRT2PI;
            g_phix[idx] = __float2bfloat16(val * cdf * m[j]);
            g_phid[idx] = __float2bfloat16((cdf + val * pdf) * m[j]);
            g_bub[idx]  = __float2bfloat16(bu[idx]);
            float sgn = (val > 0.0f) ? 1.0f : ((val < 0.0f) ? -1.0f : 0.0f);
            g_tdx[idx]  = __float2bfloat16(3.0f * td[idx] - 5.5f * val - 1e-6f * sgn
                                           + 1.5f * b_in[col]);
        }
        float c[16];
#pragma unroll
        for (int j = 0; j < 16; j++) {
            size_t idx = base + lane + 32 * j;
            c[j] = 0.5f * xt1[idx] + 0.3f * xt2[idx] + 0.2f * xt3[idx];
        }
        kwta_reg(c, m);
#pragma unroll
        for (int j = 0; j < 16; j++) {
            size_t idx = base + lane + 32 * j;
            float val = c[j];
            g_ctx[idx] = __float2bfloat16(val);
            float t = fast_tanh(GC0 * (val + GC1 * val * val * val));
            g_phic[idx] = __float2bfloat16(val * 0.5f * (1.0f + t) * m[j]);
        }
    } else if (b < nb_elem + NB_CONV) {
        // ---- weight conversion ----
        int bid = b - nb_elem;
        int n = D * D;
        for (int idx = bid * 256 + threadIdx.x; idx < n; idx += NB_CONV * 256) {
            int i = idx >> 9, j = idx & 511;
            float w = W[idx];
            g_Wb[idx]        = __float2bfloat16(w);
            g_WTb[j * D + i] = __float2bfloat16(w);
            g_V15b[idx]      = __float2bfloat16(1.5f * V[idx]);
            g_Rb[idx]        = __float2bfloat16(R[idx]);
            g_Rgb[idx]       = __float2bfloat16(Rg[idx]);
            g_Lb[idx]        = __float2bfloat16(L[idx]);
        }
    } else {
        // ---- cvec ----
        int bid = b - nb_elem - NB_CONV;
        int gw = (bid * 256 + threadIdx.x) >> 5;
        int lane = threadIdx.x & 31;
        for (int row = gw; row < D; row += NB_CVEC * 8) {
            float s = 0.0f;
            for (int j = 0; j < 16; j++) {
                int i = lane + 32 * j;
                s += b_out[i] * W[(size_t)row * D + i];
            }
#pragma unroll
            for (int o = 16; o > 0; o >>= 1) s += __shfl_xor_sync(0xffffffffu, s, o);
            if (lane == 0) g_cvec[row] = s;
        }
    }
}

// ---------------- cp.async helpers ----------------
__device__ __forceinline__ void cp16(void* s, const void* g) {
    unsigned sa = (unsigned)__cvta_generic_to_shared(s);
    asm volatile("cp.async.cg.shared.global [%0], [%1], 16;" :: "r"(sa), "l"(g));
}

// A tile: 128x64 bf16 = 1024 x 16B chunks; B tile: 64x128 bf16 = 1024 chunks
__device__ __forceinline__ void load_stage(__nv_bfloat16* stage,
                                           const __nv_bfloat16* Ag,
                                           const __nv_bfloat16* Bg,
                                           int ks, int tid) {
    int k0 = ks * BK;
    __nv_bfloat16* As = stage;
    __nv_bfloat16* Bs = stage + BM * LDAS;
#pragma unroll
    for (int t = 0; t < 4; t++) {
        int task = tid + t * 256;
        int arow = task >> 3, ach = task & 7;
        cp16(As + arow * LDAS + ach * 8, Ag + (size_t)arow * D + k0 + ach * 8);
        int brow = task >> 4, bch = task & 15;
        cp16(Bs + brow * LDBS + bch * 8, Bg + (size_t)(k0 + brow) * D + bch * 8);
    }
}

// ---------------- pipelined 128x128 tile core (nk=8, BK=64) ----------------
__device__ __forceinline__ void run_gemm(
    const __nv_bfloat16* Ag, const __nv_bfloat16* Bg,
    __nv_bfloat16* smem, int tid, int wm, int wn,
    wmma::fragment<wmma::accumulator, 16, 16, 16, float> acc[4][2]) {
    load_stage(smem + 0 * STAGE_E, Ag, Bg, 0, tid);
    asm volatile("cp.async.commit_group;" ::: "memory");
    load_stage(smem + 1 * STAGE_E, Ag, Bg, 1, tid);
    asm volatile("cp.async.commit_group;" ::: "memory");
    for (int ki = 0; ki < NK; ki++) {
        asm volatile("cp.async.wait_group 1;" ::: "memory");
        __syncthreads();
        __nv_bfloat16* As = smem + (ki % NSTAGE) * STAGE_E;
        __nv_bfloat16* Bs = As + BM * LDAS;
#pragma unroll
        for (int kk = 0; kk < BK; kk += 16) {
            wmma::fragment<wmma::matrix_a, 16, 16, 16, __nv_bfloat16, wmma::row_major> af[4];
            wmma::fragment<wmma::matrix_b, 16, 16, 16, __nv_bfloat16, wmma::row_major> bf_[2];
#pragma unroll
            for (int i = 0; i < 4; i++)
                wmma::load_matrix_sync(af[i], As + (wm * 64 + i * 16) * LDAS + kk, LDAS);
#pragma unroll
            for (int j = 0; j < 2; j++)
                wmma::load_matrix_sync(bf_[j], Bs + kk * LDBS + wn * 32 + j * 16, LDBS);
#pragma unroll
            for (int i = 0; i < 4; i++)
#pragma unroll
                for (int j = 0; j < 2; j++)
                    wmma::mma_sync(acc[i][j], af[i], bf_[j], acc[i][j]);
        }
        if (ki + 2 < NK) load_stage(smem + ((ki + 2) % NSTAGE) * STAGE_E, Ag, Bg, ki + 2, tid);
        asm volatile("cp.async.commit_group;" ::: "memory");
    }
    asm volatile("cp.async.wait_group 0;" ::: "memory");
    __syncthreads();
}

// ---------------- wwt: -(W @ W^T) via pipelined core, 16 CTAs ----------------
__global__ void __launch_bounds__(256, 2) wwt_kernel() {
    extern __shared__ unsigned char smem_raw[];
    __nv_bfloat16* smem = (__nv_bfloat16*)smem_raw;
    const int tid = threadIdx.x, wid = tid >> 5;
    const int wm = wid >> 2, wn = wid & 3;
    const int m0 = blockIdx.y * BM, n0 = blockIdx.x * BN;

    wmma::fragment<wmma::accumulator, 16, 16, 16, float> acc[4][2];
#pragma unroll
    for (int i = 0; i < 4; i++)
#pragma unroll
        for (int j = 0; j < 2; j++) wmma::fill_fragment(acc[i][j], 0.0f);

    run_gemm(g_Wb + (size_t)m0 * D, g_WTb + n0, smem, tid, wm, wn, acc);

    float* Es = (float*)smem_raw;
#pragma unroll 1
    for (int half = 0; half < 2; half++) {
        __syncthreads();
        if (wm == half)
#pragma unroll
            for (int i = 0; i < 4; i++)
#pragma unroll
                for (int j = 0; j < 2; j++)
                    wmma::store_matrix_sync(Es + (i * 16) * LDE + wn * 32 + j * 16,
                                            acc[i][j], LDE, wmma::mem_row_major);
        __syncthreads();
#pragma unroll 4
        for (int t = 0; t < 32; t++) {
            int idx = t * 256 + tid;
            int r = idx >> 7, c = idx & 127;
            g_nWWT[(size_t)(m0 + half * 64 + r) * D + n0 + c] = __float2bfloat16(-Es[r * LDE + c]);
        }
    }
}

// ---------------- main GEMM phase: 6 uniform nk=8 slices ----------------
// z0: t0 = bub@W^T      z1: t1 = phix@(-WWT)   z2: t2 = phix@L
// z3: t3 = bub@(1.5V)   z4: gate = sigmoid(ctx@Rg)   z5: rec = phic@R
__global__ void __launch_bounds__(256, 2) gemm_kernel() {
    extern __shared__ unsigned char smem_raw[];
    __nv_bfloat16* smem = (__nv_bfloat16*)smem_raw;
    float* Es = (float*)smem_raw;

    const int tid = threadIdx.x, wid = tid >> 5;
    const int wm = wid >> 2, wn = wid & 3;
    const int mode = blockIdx.z;
    const int n0 = blockIdx.x * BN, m0 = blockIdx.y * BM;

    const __nv_bfloat16 *A, *B;
    __nv_bfloat16* O;
    int sig = 0;
    switch (mode) {
        case 0: A = g_bub;  B = g_WTb;  O = g_t0; break;
        case 1: A = g_phix; B = g_nWWT; O = g_t1; break;
        case 2: A = g_phix; B = g_Lb;   O = g_t2; break;
        case 3: A = g_bub;  B = g_V15b; O = g_t3; break;
        case 4: A = g_ctx;  B = g_Rgb;  O = g_gate; sig = 1; break;
        default: A = g_phic; B = g_Rb;  O = g_rec; break;
    }

    wmma::fragment<wmma::accumulator, 16, 16, 16, float> acc[4][2];
#pragma unroll
    for (int i = 0; i < 4; i++)
#pragma unroll
        for (int j = 0; j < 2; j++) wmma::fill_fragment(acc[i][j], 0.0f);

    run_gemm(A + (size_t)m0 * D, B + n0, smem, tid, wm, wn, acc);

#pragma unroll 1
    for (int half = 0; half < 2; half++) {
        __syncthreads();
        if (wm == half)
#pragma unroll
            for (int i = 0; i < 4; i++)
#pragma unroll
                for (int j = 0; j < 2; j++)
                    wmma::store_matrix_sync(Es + (i * 16) * LDE + wn * 32 + j * 16,
                                            acc[i][j], LDE, wmma::mem_row_major);
        __syncthreads();
#pragma unroll 4
        for (int t = 0; t < 32; t++) {
            int idx = t * 256 + tid;
            int r = idx >> 7, c = idx & 127;
            size_t gi = (size_t)(m0 + half * 64 + r) * D + n0 + c;
            float v = Es[r * LDE + c];
            if (sig) v = 1.0f / (1.0f + __expf(-v));
            O[gi] = __float2bfloat16(v);
        }
    }
}

// ---------------- g = (t0+t1-cvec)*phid + t2 + t3 + tdx + rec*gate ---------
__global__ void __launch_bounds__(256) gfuse_kernel() {
    __shared__ float red[256];
    const int tid = threadIdx.x;
    const int base = blockIdx.x * 2048;          // uint2 (4xbf16) units
    const uint2* t04 = (const uint2*)g_t0;
    const uint2* t14 = (const uint2*)g_t1;
    const uint2* t24 = (const uint2*)g_t2;
    const uint2* t34 = (const uint2*)g_t3;
    const uint2* pd4 = (const uint2*)g_phid;
    const uint2* tx4 = (const uint2*)g_tdx;
    const uint2* rc4 = (const uint2*)g_rec;
    const uint2* gt4 = (const uint2*)g_gate;
    const float4* cv4 = (const float4*)g_cvec;
    uint2* gg4 = (uint2*)g_g;

    float ss = 0.0f;
#pragma unroll
    for (int t = 0; t < 8; t++) {
        int i = base + t * 256 + tid;
        float4 cv = cv4[i & 127];
        uint2 u0 = t04[i], u1 = t14[i], u2 = t24[i], u3 = t34[i];
        uint2 up = pd4[i], ut = tx4[i], ur = rc4[i], ug = gt4[i];
        float2 a0 = __bfloat1622float2(*(__nv_bfloat162*)&u0.x);
        float2 a1 = __bfloat1622float2(*(__nv_bfloat162*)&u0.y);
        float2 b0 = __bfloat1622float2(*(__nv_bfloat162*)&u1.x);
        float2 b1 = __bfloat1622float2(*(__nv_bfloat162*)&u1.y);
        float2 c0 = __bfloat1622float2(*(__nv_bfloat162*)&u2.x);
        float2 c1 = __bfloat1622float2(*(__nv_bfloat162*)&u2.y);
        float2 d0 = __bfloat1622float2(*(__nv_bfloat162*)&u3.x);
        float2 d1 = __bfloat1622float2(*(__nv_bfloat162*)&u3.y);
        float2 p0 = __bfloat1622float2(*(__nv_bfloat162*)&up.x);
        float2 p1 = __bfloat1622float2(*(__nv_bfloat162*)&up.y);
        float2 x0 = __bfloat1622float2(*(__nv_bfloat162*)&ut.x);
        float2 x1 = __bfloat1622float2(*(__nv_bfloat162*)&ut.y);
        float2 r0 = __bfloat1622float2(*(__nv_bfloat162*)&ur.x);
        float2 r1 = __bfloat1622float2(*(__nv_bfloat162*)&ur.y);
        float2 s0 = __bfloat1622float2(*(__nv_bfloat162*)&ug.x);
        float2 s1 = __bfloat1622float2(*(__nv_bfloat162*)&ug.y);
        float ga = (a0.x + b0.x - cv.x) * p0.x + c0.x + d0.x + x0.x + r0.x * s0.x;
        float gb = (a0.y + b0.y - cv.y) * p0.y + c0.y + d0.y + x0.y + r0.y * s0.y;
        float gc = (a1.x + b1.x - cv.z) * p1.x + c1.x + d1.x + x1.x + r1.x * s1.x;
        float gd = (a1.y + b1.y - cv.w) * p1.y + c1.y + d1.y + x1.y + r1.y * s1.y;
        uint2 o;
        __nv_bfloat162 lo = __floats2bfloat162_rn(ga, gb);
        __nv_bfloat162 hi = __floats2bfloat162_rn(gc, gd);
        o.x = *(unsigned*)&lo; o.y = *(unsigned*)&hi;
        gg4[i] = o;
        ss += ga * ga + gb * gb + gc * gc + gd * gd;
    }
    red[tid] = ss;
    __syncthreads();
    for (int o = 128; o > 0; o >>= 1) {
        if (tid < o) red[tid] += red[tid + o];
        __syncthreads();
    }
    if (tid == 0) g_part[blockIdx.x] = red[0];
}

// ---------------- global norm -> clip scale ----------------
__global__ void reduce_scale_kernel(const int* __restrict__ step_i, int nparts) {
    __shared__ float red[256];
    float s = 0.0f;
    for (int i = threadIdx.x; i < nparts; i += 256) s += g_part[i];
    red[threadIdx.x] = s;
    __syncthreads();
    for (int o = 128; o > 0; o >>= 1) {
        if (threadIdx.x < o) red[threadIdx.x] += red[threadIdx.x + o];
        __syncthreads();
    }
    if (threadIdx.x == 0) {
        float eta = 0.8f / (1.0f + 0.1f * (float)step_i[0]);
        float cc = 0.5f * eta;                   // TAU * eta
        float n = cc * sqrtf(red[0]);
        float sc = (n > 1.0f) ? (1.0f / (n + 1e-8f)) : 1.0f;
        g_scalef = cc * sc;
    }
}

// ---------------- finalize: x_new = clip(x + g*scale, -5, 5) ----------------
__global__ void finalize_kernel(const float* __restrict__ x, float* __restrict__ out, int n4) {
    float f = g_scalef;
    const float4* x4 = (const float4*)x;
    const uint2* gg = (const uint2*)g_g;
    float4* o4 = (float4*)out;
    for (int i = blockIdx.x * blockDim.x + threadIdx.x; i < n4; i += gridDim.x * blockDim.x) {
        float4 xv = x4[i];
        uint2 gpack = gg[i];
        float2 g0 = __bfloat1622float2(*(__nv_bfloat162*)&gpack.x);
        float2 g1 = __bfloat1622float2(*(__nv_bfloat162*)&gpack.y);
        float4 o;
        o.x = fminf(5.0f, fmaxf(-5.0f, xv.x + g0.x * f));
        o.y = fminf(5.0f, fmaxf(-5.0f, xv.y + g0.y * f));
        o.z = fminf(5.0f, fmaxf(-5.0f, xv.z + g1.x * f));
        o.w = fminf(5.0f, fmaxf(-5.0f, xv.w + g1.y * f));
        o4[i] = o;
    }
}

extern "C" void kernel_launch(void* const* d_in, const int* in_sizes, int n_in,
                              void* d_out, int out_size) {
    const float* bu    = (const float*)d_in[0];
    const float* td    = (const float*)d_in[1];
    const float* x     = (const float*)d_in[2];
    const float* xt1   = (const float*)d_in[3];
    const float* xt2   = (const float*)d_in[4];
    const float* xt3   = (const float*)d_in[5];
    const float* V     = (const float*)d_in[6];
    const float* b_in  = (const float*)d_in[7];
    const float* W     = (const float*)d_in[8];
    const float* b_out = (const float*)d_in[9];
    const float* R     = (const float*)d_in[10];
    const float* Rg    = (const float*)d_in[11];
    const float* L     = (const float*)d_in[12];
    const int*   step  = (const int*)d_in[13];

    int Btot = in_sizes[2] / D;
    if (Btot > MAXB) Btot = MAXB;
    int mtiles = Btot / BM;             // 64
    int nb_elem = Btot / 8;             // 1024

    cudaFuncSetAttribute(gemm_kernel, cudaFuncAttributeMaxDynamicSharedMemorySize, SMEM_GEMM);
    cudaFuncSetAttribute(wwt_kernel, cudaFuncAttributeMaxDynamicSharedMemorySize, SMEM_GEMM);

    prep_kernel<<<nb_elem + NB_CONV + NB_CVEC, 256>>>(x, xt1, xt2, xt3, bu, td,
                                                      W, V, R, Rg, L, b_out, b_in, nb_elem);
    wwt_kernel<<<dim3(4, 4), 256, SMEM_GEMM>>>();
    gemm_kernel<<<dim3(D / BN, mtiles, 6), 256, SMEM_GEMM>>>();
    gfuse_kernel<<<(Btot * D) / 8192, 256>>>();
    reduce_scale_kernel<<<1, 256>>>(step, (Btot * D) / 8192);
    finalize_kernel<<<1024, 256>>>(x, (float*)d_out, Btot * D / 4);
}